// round 1
// baseline (speedup 1.0000x reference)
#include <cuda_runtime.h>
#include <math.h>

// Problem constants
#define BB 8
#define CC 512
#define NN 2304   // 48*48

// Scratch (device globals; allocation-free per harness rules)
__device__ float g_eb [NN * NN];        // exp(pos_bias)          21.2 MB
__device__ float g_sq [BB * NN * CC];   // sigmoid(q)             37.7 MB
__device__ float g_ek [BB * NN * CC];   // exp(k)                 37.7 MB
__device__ float g_ekv[BB * NN * CC];   // exp(k)*v               37.7 MB

// Tiling
#define BM 128
#define BN 64
#define BK 16
#define AST 132   // padded stride for As (kills transpose-store conflicts)
#define BST 68    // padded stride for Bs

// ---------------------------------------------------------------------------
// Kernel 1: eb = exp(pos_bias)   (vectorized elementwise)
// ---------------------------------------------------------------------------
__global__ void eb_kernel(const float* __restrict__ pb) {
    int idx = blockIdx.x * blockDim.x + threadIdx.x;   // float4 index
    const float4* in = (const float4*)pb;
    float4 p = in[idx];
    float4 o;
    o.x = expf(p.x); o.y = expf(p.y); o.z = expf(p.z); o.w = expf(p.w);
    ((float4*)g_eb)[idx] = o;
}

// ---------------------------------------------------------------------------
// Kernel 2: sq = sigmoid(xf @ Wq^T + bq)
// A[k=c'][m=i] = x[b, c', i]  (already K-major rows, contiguous in i)
// B[k=c'][n=c] = Wq[c, c']    (contiguous in k -> transpose into smem)
// ---------------------------------------------------------------------------
__global__ __launch_bounds__(256)
void q_gemm(const float* __restrict__ x, const float* __restrict__ Wq,
            const float* __restrict__ bq) {
    __shared__ float As[BK][AST];
    __shared__ float Bs[BK][BST];

    const int b  = blockIdx.z;
    const int m0 = blockIdx.x * BM;
    const int n0 = blockIdx.y * BN;
    const int tid = threadIdx.x;
    const int ty = tid >> 4, tx = tid & 15;
    const int tm0 = ty * 8, tn0 = tx * 4;

    const float* A = x + (size_t)b * CC * NN;
    float acc[8][4] = {};

    for (int k0 = 0; k0 < CC; k0 += BK) {
        // A tile: 16 x 128 = 512 float4, 2 per thread
        #pragma unroll
        for (int r = 0; r < 2; r++) {
            int v = tid + r * 256;
            int kr = v >> 5, mc = (v & 31) << 2;
            float4 a = *(const float4*)(A + (size_t)(k0 + kr) * NN + m0 + mc);
            *(float4*)(&As[kr][mc]) = a;
        }
        // B tile with transpose: 16 x 64 = 256 float4, 1 per thread
        {
            int cidx = tid >> 2, k4 = (tid & 3) << 2;
            float4 w = *(const float4*)(Wq + (size_t)(n0 + cidx) * CC + k0 + k4);
            Bs[k4 + 0][cidx] = w.x;
            Bs[k4 + 1][cidx] = w.y;
            Bs[k4 + 2][cidx] = w.z;
            Bs[k4 + 3][cidx] = w.w;
        }
        __syncthreads();
        #pragma unroll
        for (int k = 0; k < BK; k++) {
            float a[8], bv[4];
            *(float4*)(a)     = *(float4*)(&As[k][tm0]);
            *(float4*)(a + 4) = *(float4*)(&As[k][tm0 + 4]);
            *(float4*)(bv)    = *(float4*)(&Bs[k][tn0]);
            #pragma unroll
            for (int i = 0; i < 8; i++)
                #pragma unroll
                for (int j = 0; j < 4; j++)
                    acc[i][j] += a[i] * bv[j];
        }
        __syncthreads();
    }

    float4 bias = *(const float4*)(bq + n0 + tn0);
    float* out = g_sq + (size_t)b * NN * CC;
    #pragma unroll
    for (int i = 0; i < 8; i++) {
        float4 o;
        o.x = 1.f / (1.f + expf(-(acc[i][0] + bias.x)));
        o.y = 1.f / (1.f + expf(-(acc[i][1] + bias.y)));
        o.z = 1.f / (1.f + expf(-(acc[i][2] + bias.z)));
        o.w = 1.f / (1.f + expf(-(acc[i][3] + bias.w)));
        *(float4*)(out + (size_t)(m0 + tm0 + i) * CC + n0 + tn0) = o;
    }
}

// ---------------------------------------------------------------------------
// Kernel 3: k = yf@Wk^T+bk, v = yf@Wv^T+bv  (dual accumulators, shared A)
//           epilogue: ek = exp(k), ekv = ek * v
// ---------------------------------------------------------------------------
__global__ __launch_bounds__(256)
void kv_gemm(const float* __restrict__ y, const float* __restrict__ Wk,
             const float* __restrict__ bk, const float* __restrict__ Wv,
             const float* __restrict__ bv) {
    __shared__ float As[BK][AST];
    __shared__ float Bk[BK][BST];
    __shared__ float Bv[BK][BST];

    const int b  = blockIdx.z;
    const int m0 = blockIdx.x * BM;
    const int n0 = blockIdx.y * BN;
    const int tid = threadIdx.x;
    const int ty = tid >> 4, tx = tid & 15;
    const int tm0 = ty * 8, tn0 = tx * 4;

    const float* A = y + (size_t)b * CC * NN;
    float acck[8][4] = {};
    float accv[8][4] = {};

    for (int k0 = 0; k0 < CC; k0 += BK) {
        #pragma unroll
        for (int r = 0; r < 2; r++) {
            int v = tid + r * 256;
            int kr = v >> 5, mc = (v & 31) << 2;
            float4 a = *(const float4*)(A + (size_t)(k0 + kr) * NN + m0 + mc);
            *(float4*)(&As[kr][mc]) = a;
        }
        {
            int cidx = tid >> 2, k4 = (tid & 3) << 2;
            float4 wk = *(const float4*)(Wk + (size_t)(n0 + cidx) * CC + k0 + k4);
            Bk[k4 + 0][cidx] = wk.x; Bk[k4 + 1][cidx] = wk.y;
            Bk[k4 + 2][cidx] = wk.z; Bk[k4 + 3][cidx] = wk.w;
            float4 wv = *(const float4*)(Wv + (size_t)(n0 + cidx) * CC + k0 + k4);
            Bv[k4 + 0][cidx] = wv.x; Bv[k4 + 1][cidx] = wv.y;
            Bv[k4 + 2][cidx] = wv.z; Bv[k4 + 3][cidx] = wv.w;
        }
        __syncthreads();
        #pragma unroll
        for (int k = 0; k < BK; k++) {
            float a[8], bk_[4], bv_[4];
            *(float4*)(a)     = *(float4*)(&As[k][tm0]);
            *(float4*)(a + 4) = *(float4*)(&As[k][tm0 + 4]);
            *(float4*)(bk_)   = *(float4*)(&Bk[k][tn0]);
            *(float4*)(bv_)   = *(float4*)(&Bv[k][tn0]);
            #pragma unroll
            for (int i = 0; i < 8; i++) {
                #pragma unroll
                for (int j = 0; j < 4; j++) {
                    acck[i][j] += a[i] * bk_[j];
                    accv[i][j] += a[i] * bv_[j];
                }
            }
        }
        __syncthreads();
    }

    float4 biask = *(const float4*)(bk + n0 + tn0);
    float4 biasv = *(const float4*)(bv + n0 + tn0);
    float* oek  = g_ek  + (size_t)b * NN * CC;
    float* oekv = g_ekv + (size_t)b * NN * CC;
    #pragma unroll
    for (int i = 0; i < 8; i++) {
        float ek0 = expf(acck[i][0] + biask.x);
        float ek1 = expf(acck[i][1] + biask.y);
        float ek2 = expf(acck[i][2] + biask.z);
        float ek3 = expf(acck[i][3] + biask.w);
        float4 e; e.x = ek0; e.y = ek1; e.z = ek2; e.w = ek3;
        float4 ev;
        ev.x = ek0 * (accv[i][0] + biasv.x);
        ev.y = ek1 * (accv[i][1] + biasv.y);
        ev.z = ek2 * (accv[i][2] + biasv.z);
        ev.w = ek3 * (accv[i][3] + biasv.w);
        size_t off = (size_t)(m0 + tm0 + i) * CC + n0 + tn0;
        *(float4*)(oek  + off) = e;
        *(float4*)(oekv + off) = ev;
    }
}

// ---------------------------------------------------------------------------
// Kernel 4: num = eb @ ekv, den = eb @ ek  (dual output, shared eb tile);
//           epilogue: out[b,c,i] = sq[b,i,c] * num/den  (writes (B,C,H,W))
// ---------------------------------------------------------------------------
__global__ __launch_bounds__(256)
void attn_gemm(float* __restrict__ out) {
    __shared__ float As[BK][AST];    // eb tile, transposed to [k][i]
    __shared__ float B1[BK][BST];    // ekv
    __shared__ float B2[BK][BST];    // ek

    const int b  = blockIdx.z;
    const int m0 = blockIdx.x * BM;   // i (query)
    const int n0 = blockIdx.y * BN;   // d (channel)
    const int tid = threadIdx.x;
    const int ty = tid >> 4, tx = tid & 15;
    const int tm0 = ty * 8, tn0 = tx * 4;

    const float* ekv = g_ekv + (size_t)b * NN * CC;
    const float* ek  = g_ek  + (size_t)b * NN * CC;

    float accN[8][4] = {};
    float accD[8][4] = {};

    for (int k0 = 0; k0 < NN; k0 += BK) {
        // eb tile: 128 x 16, transpose into As[k][i]
        #pragma unroll
        for (int r = 0; r < 2; r++) {
            int v = tid + r * 256;
            int irow = v >> 2;           // 0..127
            int k4 = (v & 3) << 2;
            float4 a = *(const float4*)(g_eb + (size_t)(m0 + irow) * NN + k0 + k4);
            As[k4 + 0][irow] = a.x;
            As[k4 + 1][irow] = a.y;
            As[k4 + 2][irow] = a.z;
            As[k4 + 3][irow] = a.w;
        }
        // ekv / ek tiles: direct float4
        {
            int kr = tid >> 4, c4 = (tid & 15) << 2;
            *(float4*)(&B1[kr][c4]) =
                *(const float4*)(ekv + (size_t)(k0 + kr) * CC + n0 + c4);
            *(float4*)(&B2[kr][c4]) =
                *(const float4*)(ek  + (size_t)(k0 + kr) * CC + n0 + c4);
        }
        __syncthreads();
        #pragma unroll
        for (int k = 0; k < BK; k++) {
            float a[8], b1[4], b2[4];
            *(float4*)(a)     = *(float4*)(&As[k][tm0]);
            *(float4*)(a + 4) = *(float4*)(&As[k][tm0 + 4]);
            *(float4*)(b1)    = *(float4*)(&B1[k][tn0]);
            *(float4*)(b2)    = *(float4*)(&B2[k][tn0]);
            #pragma unroll
            for (int i = 0; i < 8; i++) {
                #pragma unroll
                for (int j = 0; j < 4; j++) {
                    accN[i][j] += a[i] * b1[j];
                    accD[i][j] += a[i] * b2[j];
                }
            }
        }
        __syncthreads();
    }

    // Epilogue: sigmoid(q) * num/den, write to (B, C, n) layout
    const float* sq = g_sq + (size_t)b * NN * CC;
    float* o = out + (size_t)b * CC * NN;
    #pragma unroll
    for (int i = 0; i < 8; i++) {
        int gi = m0 + tm0 + i;
        float4 s = *(const float4*)(sq + (size_t)gi * CC + n0 + tn0);
        float r0 = s.x * accN[i][0] / accD[i][0];
        float r1 = s.y * accN[i][1] / accD[i][1];
        float r2 = s.z * accN[i][2] / accD[i][2];
        float r3 = s.w * accN[i][3] / accD[i][3];
        o[(size_t)(n0 + tn0 + 0) * NN + gi] = r0;
        o[(size_t)(n0 + tn0 + 1) * NN + gi] = r1;
        o[(size_t)(n0 + tn0 + 2) * NN + gi] = r2;
        o[(size_t)(n0 + tn0 + 3) * NN + gi] = r3;
    }
}

// ---------------------------------------------------------------------------
// Launch
// ---------------------------------------------------------------------------
extern "C" void kernel_launch(void* const* d_in, const int* in_sizes, int n_in,
                              void* d_out, int out_size) {
    const float* x  = (const float*)d_in[0];
    const float* y  = (const float*)d_in[1];
    const float* Wq = (const float*)d_in[2];
    const float* bq = (const float*)d_in[3];
    const float* Wk = (const float*)d_in[4];
    const float* bk = (const float*)d_in[5];
    const float* Wv = (const float*)d_in[6];
    const float* bv = (const float*)d_in[7];
    const float* pb = (const float*)d_in[8];
    float* out = (float*)d_out;

    // 1) eb = exp(pos_bias): NN*NN/4 float4 elements
    eb_kernel<<<(NN * NN / 4) / 256, 256>>>(pb);

    dim3 grid(NN / BM, CC / BN, BB);   // (18, 8, 8)

    // 2) sq = sigmoid(q)
    q_gemm<<<grid, 256>>>(x, Wq, bq);

    // 3) ek, ekv
    kv_gemm<<<grid, 256>>>(y, Wk, bk, Wv, bv);

    // 4) num/den GEMM + final epilogue
    attn_gemm<<<grid, 256>>>(out);
}

// round 2
// speedup vs baseline: 2.1641x; 2.1641x over previous
#include <cuda_runtime.h>
#include <math.h>
#include <stdint.h>

// Problem constants
#define BB 8
#define CC 512
#define NN 2304          // 48*48
#define NKV 1024         // concat width: [ekv | ek]

// ---------------------------------------------------------------------------
// Scratch (device globals; allocation-free per harness rules)
// ---------------------------------------------------------------------------
__device__ float g_eb  [NN * NN];          // tf32(exp(pos_bias))         21.2 MB
__device__ float g_xc  [BB * CC * NN];     // tf32(x)                     37.7 MB
__device__ float g_yc  [BB * CC * NN];     // tf32(y)                     37.7 MB
__device__ float g_wq  [CC * CC];          // tf32(Wq)
__device__ float g_wk  [CC * CC];
__device__ float g_wv  [CC * CC];
__device__ float g_qraw[BB * NN * CC];     // q pre-activation            37.7 MB
__device__ float g_kvraw[BB * NN * NKV];   // [k | v] raw                 75.5 MB
__device__ float g_sq  [BB * NN * CC];     // sigmoid(q)                  37.7 MB
__device__ float g_kv  [BB * NN * NKV];    // tf32([ek*v | ek])           75.5 MB
__device__ float g_nd  [BB * NN * NKV];    // [num | den]                 75.5 MB

// ---------------------------------------------------------------------------
// Helpers
// ---------------------------------------------------------------------------
__device__ __forceinline__ float f2tf(float x) {
    uint32_t r;
    asm("cvt.rna.tf32.f32 %0, %1;" : "=r"(r) : "f"(x));
    return __uint_as_float(r);
}

__device__ __forceinline__ void mma_tf32(float c[4], const uint32_t a[4],
                                         const uint32_t b[2]) {
    asm volatile(
        "mma.sync.aligned.m16n8k8.row.col.f32.tf32.tf32.f32 "
        "{%0,%1,%2,%3},{%4,%5,%6,%7},{%8,%9},{%0,%1,%2,%3};\n"
        : "+f"(c[0]), "+f"(c[1]), "+f"(c[2]), "+f"(c[3])
        : "r"(a[0]), "r"(a[1]), "r"(a[2]), "r"(a[3]), "r"(b[0]), "r"(b[1]));
}

// ---------------------------------------------------------------------------
// Elementwise prep kernels
// ---------------------------------------------------------------------------
__global__ void cvt_kernel(const float* __restrict__ src, float* __restrict__ dst) {
    int idx = blockIdx.x * blockDim.x + threadIdx.x;
    float4 p = ((const float4*)src)[idx];
    float4 o;
    o.x = f2tf(p.x); o.y = f2tf(p.y); o.z = f2tf(p.z); o.w = f2tf(p.w);
    ((float4*)dst)[idx] = o;
}

__global__ void eb_kernel(const float* __restrict__ pb) {
    int idx = blockIdx.x * blockDim.x + threadIdx.x;
    float4 p = ((const float4*)pb)[idx];
    float4 o;
    o.x = f2tf(expf(p.x)); o.y = f2tf(expf(p.y));
    o.z = f2tf(expf(p.z)); o.w = f2tf(expf(p.w));
    ((float4*)g_eb)[idx] = o;
}

// sq = sigmoid(qraw + bq); g_kv = [tf32(exp(k+bk)*(v+bv)) | tf32(exp(k+bk))]
__global__ void transform_kernel(const float* __restrict__ bq,
                                 const float* __restrict__ bk,
                                 const float* __restrict__ bv) {
    int idx = blockIdx.x * blockDim.x + threadIdx.x;   // over BB*NN*128 float4
    int c4  = idx & 127;                               // channel/4
    int bj  = idx >> 7;                                // b*NN + j

    float4 q4 = ((const float4*)g_qraw)[idx];
    float4 k4 = ((const float4*)g_kvraw)[(size_t)bj * 256 + c4];
    float4 v4 = ((const float4*)g_kvraw)[(size_t)bj * 256 + 128 + c4];
    float4 bq4 = ((const float4*)bq)[c4];
    float4 bk4 = ((const float4*)bk)[c4];
    float4 bv4 = ((const float4*)bv)[c4];

    float4 s;
    s.x = 1.f / (1.f + expf(-(q4.x + bq4.x)));
    s.y = 1.f / (1.f + expf(-(q4.y + bq4.y)));
    s.z = 1.f / (1.f + expf(-(q4.z + bq4.z)));
    s.w = 1.f / (1.f + expf(-(q4.w + bq4.w)));
    ((float4*)g_sq)[idx] = s;

    float e0 = expf(k4.x + bk4.x), e1 = expf(k4.y + bk4.y);
    float e2 = expf(k4.z + bk4.z), e3 = expf(k4.w + bk4.w);
    float4 ekv, ek;
    ekv.x = f2tf(e0 * (v4.x + bv4.x)); ekv.y = f2tf(e1 * (v4.y + bv4.y));
    ekv.z = f2tf(e2 * (v4.z + bv4.z)); ekv.w = f2tf(e3 * (v4.w + bv4.w));
    ek.x = f2tf(e0); ek.y = f2tf(e1); ek.z = f2tf(e2); ek.w = f2tf(e3);
    ((float4*)g_kv)[(size_t)bj * 256 + c4]       = ekv;   // num half
    ((float4*)g_kv)[(size_t)bj * 256 + 128 + c4] = ek;    // den half
}

// ---------------------------------------------------------------------------
// tf32 GEMM core: C[M,N] += A @ B, BM=128 BN=256 BK=32, 256 thr, warp 64x64
// TA: A global is [M][K] (transpose into smem), else [K][M]
// TB: B global is [N][K] (transpose into smem), else [K][N]
// smem: As[32][136], Bs[32][264]  (strides ≡ 8 mod 32 → conflict-free frags)
// ---------------------------------------------------------------------------
#define SA 136
#define SB 264
#define GEMM_SMEM ((32 * SA + 32 * SB) * 4)

template <bool TA, bool TB>
__global__ void __launch_bounds__(256)
gemm_tf32(const float* __restrict__ Ag, const float* __restrict__ Bg,
          float* __restrict__ Cg, int K, int lda, int ldb, int ldc,
          size_t strideA, size_t strideB, size_t strideC) {
    extern __shared__ float sm[];
    float* As = sm;
    float* Bs = sm + 32 * SA;

    const int b  = blockIdx.z;
    const int m0 = blockIdx.x * 128;
    const int n0 = blockIdx.y * 256;
    const int tid = threadIdx.x;

    Ag += (size_t)b * strideA;
    Bg += (size_t)b * strideB;
    Cg += (size_t)b * strideC;

    const int wid = tid >> 5;
    const int mw = (wid & 1) * 64;      // warp m offset
    const int nw = (wid >> 1) * 64;     // warp n offset
    const int lane = tid & 31;
    const int lq = lane & 3;            // k-within-frag
    const int lr = lane >> 2;           // row/col-within-frag

    float acc[4][8][4];
    #pragma unroll
    for (int i = 0; i < 4; i++)
        #pragma unroll
        for (int j = 0; j < 8; j++)
            #pragma unroll
            for (int l = 0; l < 4; l++) acc[i][j][l] = 0.f;

    float4 ra[4], rb[8];

    auto loadA = [&](int k0) {
        #pragma unroll
        for (int r = 0; r < 4; r++) {
            int v = tid + r * 256;
            if (TA) {   // A[m][k]
                int mr = v & 127, kc = (v >> 7) << 2;
                ra[r] = *(const float4*)(Ag + (size_t)(m0 + mr) * lda + k0 + kc);
            } else {    // A[k][m]
                int kr = v >> 5, mc = (v & 31) << 2;
                ra[r] = *(const float4*)(Ag + (size_t)(k0 + kr) * lda + m0 + mc);
            }
        }
    };
    auto loadB = [&](int k0) {
        #pragma unroll
        for (int r = 0; r < 8; r++) {
            int v = tid + r * 256;
            if (TB) {   // B[n][k]
                int nr = v & 255, kc = (v >> 8) << 2;
                rb[r] = *(const float4*)(Bg + (size_t)(n0 + nr) * ldb + k0 + kc);
            } else {    // B[k][n]
                int kr = v >> 6, nc = (v & 63) << 2;
                rb[r] = *(const float4*)(Bg + (size_t)(k0 + kr) * ldb + n0 + nc);
            }
        }
    };
    auto storeA = [&]() {
        #pragma unroll
        for (int r = 0; r < 4; r++) {
            int v = tid + r * 256;
            if (TA) {
                int mr = v & 127, kc = (v >> 7) << 2;
                As[(kc + 0) * SA + mr] = ra[r].x;
                As[(kc + 1) * SA + mr] = ra[r].y;
                As[(kc + 2) * SA + mr] = ra[r].z;
                As[(kc + 3) * SA + mr] = ra[r].w;
            } else {
                int kr = v >> 5, mc = (v & 31) << 2;
                *(float4*)(As + kr * SA + mc) = ra[r];
            }
        }
    };
    auto storeB = [&]() {
        #pragma unroll
        for (int r = 0; r < 8; r++) {
            int v = tid + r * 256;
            if (TB) {
                int nr = v & 255, kc = (v >> 8) << 2;
                Bs[(kc + 0) * SB + nr] = rb[r].x;
                Bs[(kc + 1) * SB + nr] = rb[r].y;
                Bs[(kc + 2) * SB + nr] = rb[r].z;
                Bs[(kc + 3) * SB + nr] = rb[r].w;
            } else {
                int kr = v >> 6, nc = (v & 63) << 2;
                *(float4*)(Bs + kr * SB + nc) = rb[r];
            }
        }
    };

    loadA(0); loadB(0);
    storeA(); storeB();
    __syncthreads();

    for (int k0 = 0; k0 < K; k0 += 32) {
        bool more = (k0 + 32) < K;
        if (more) { loadA(k0 + 32); loadB(k0 + 32); }

        #pragma unroll
        for (int ka = 0; ka < 4; ka++) {
            uint32_t af[4][4], bf[8][2];
            #pragma unroll
            for (int mi = 0; mi < 4; mi++) {
                int base = (8 * ka + lq) * SA + mw + 16 * mi + lr;
                af[mi][0] = __float_as_uint(As[base]);
                af[mi][1] = __float_as_uint(As[base + 8]);
                af[mi][2] = __float_as_uint(As[base + 4 * SA]);
                af[mi][3] = __float_as_uint(As[base + 4 * SA + 8]);
            }
            #pragma unroll
            for (int ni = 0; ni < 8; ni++) {
                int base = (8 * ka + lq) * SB + nw + 8 * ni + lr;
                bf[ni][0] = __float_as_uint(Bs[base]);
                bf[ni][1] = __float_as_uint(Bs[base + 4 * SB]);
            }
            #pragma unroll
            for (int mi = 0; mi < 4; mi++)
                #pragma unroll
                for (int ni = 0; ni < 8; ni++)
                    mma_tf32(acc[mi][ni], af[mi], bf[ni]);
        }
        __syncthreads();
        if (more) {
            storeA(); storeB();
            __syncthreads();
        }
    }

    // Epilogue: plain fp32 store (float2 per half-atom)
    const int cm = m0 + mw;
    const int cn = n0 + nw;
    #pragma unroll
    for (int mi = 0; mi < 4; mi++) {
        #pragma unroll
        for (int ni = 0; ni < 8; ni++) {
            int row = cm + 16 * mi + lr;
            int col = cn + 8 * ni + 2 * lq;
            float2 v0 = make_float2(acc[mi][ni][0], acc[mi][ni][1]);
            float2 v1 = make_float2(acc[mi][ni][2], acc[mi][ni][3]);
            *(float2*)(Cg + (size_t)row * ldc + col) = v0;
            *(float2*)(Cg + (size_t)(row + 8) * ldc + col) = v1;
        }
    }
}

// ---------------------------------------------------------------------------
// Final epilogue: out[b,c,i] = sq[b,i,c] * num/den  with 32x32 smem transpose
// ---------------------------------------------------------------------------
__global__ void __launch_bounds__(256)
final_kernel(float* __restrict__ out) {
    __shared__ float ts[32][33];
    const int b  = blockIdx.z;
    const int i0 = blockIdx.x * 32;
    const int c0 = blockIdx.y * 32;
    const int tid = threadIdx.x;
    const int cl = tid & 31;
    const int il = tid >> 5;

    #pragma unroll
    for (int r = 0; r < 4; r++) {
        int i = il + 8 * r;
        size_t ndBase = ((size_t)b * NN + i0 + i) * NKV + c0 + cl;
        float num = g_nd[ndBase];
        float den = g_nd[ndBase + 512];
        float s   = g_sq[((size_t)b * NN + i0 + i) * CC + c0 + cl];
        ts[i][cl] = s * num / den;
    }
    __syncthreads();
    #pragma unroll
    for (int r = 0; r < 4; r++) {
        int c = il + 8 * r;
        out[((size_t)b * CC + c0 + c) * NN + i0 + cl] = ts[cl][c];
    }
}

// ---------------------------------------------------------------------------
// Launch
// ---------------------------------------------------------------------------
extern "C" void kernel_launch(void* const* d_in, const int* in_sizes, int n_in,
                              void* d_out, int out_size) {
    const float* x  = (const float*)d_in[0];
    const float* y  = (const float*)d_in[1];
    const float* Wq = (const float*)d_in[2];
    const float* bq = (const float*)d_in[3];
    const float* Wk = (const float*)d_in[4];
    const float* bk = (const float*)d_in[5];
    const float* Wv = (const float*)d_in[6];
    const float* bv = (const float*)d_in[7];
    const float* pb = (const float*)d_in[8];
    float* out = (float*)d_out;

    static bool attr_done = false;
    if (!attr_done) {
        cudaFuncSetAttribute(gemm_tf32<false, true>,
                             cudaFuncAttributeMaxDynamicSharedMemorySize, GEMM_SMEM);
        cudaFuncSetAttribute(gemm_tf32<true, false>,
                             cudaFuncAttributeMaxDynamicSharedMemorySize, GEMM_SMEM);
        attr_done = true;
    }

    float *p_eb, *p_xc, *p_yc, *p_wq, *p_wk, *p_wv;
    float *p_qraw, *p_kvraw, *p_kv, *p_nd;
    cudaGetSymbolAddress((void**)&p_eb, g_eb);
    cudaGetSymbolAddress((void**)&p_xc, g_xc);
    cudaGetSymbolAddress((void**)&p_yc, g_yc);
    cudaGetSymbolAddress((void**)&p_wq, g_wq);
    cudaGetSymbolAddress((void**)&p_wk, g_wk);
    cudaGetSymbolAddress((void**)&p_wv, g_wv);
    cudaGetSymbolAddress((void**)&p_qraw, g_qraw);
    cudaGetSymbolAddress((void**)&p_kvraw, g_kvraw);
    cudaGetSymbolAddress((void**)&p_kv, g_kv);
    cudaGetSymbolAddress((void**)&p_nd, g_nd);

    // 1) tf32 pre-conversion + eb
    cvt_kernel<<<BB * CC * NN / 4 / 256, 256>>>(x, p_xc);
    cvt_kernel<<<BB * CC * NN / 4 / 256, 256>>>(y, p_yc);
    cvt_kernel<<<CC * CC / 4 / 256, 256>>>(Wq, p_wq);
    cvt_kernel<<<CC * CC / 4 / 256, 256>>>(Wk, p_wk);
    cvt_kernel<<<CC * CC / 4 / 256, 256>>>(Wv, p_wv);
    eb_kernel<<<NN * NN / 4 / 256, 256>>>(pb);

    // 2) Projections: q, k, v  (A = [K=C][M=n] K-major; B = W [N][K])
    dim3 gp(NN / 128, CC / 256, BB);   // (18, 2, 8)
    gemm_tf32<false, true><<<gp, 256, GEMM_SMEM>>>(
        p_xc, p_wq, p_qraw, CC, NN, CC, CC,
        (size_t)CC * NN, 0, (size_t)NN * CC);
    gemm_tf32<false, true><<<gp, 256, GEMM_SMEM>>>(
        p_yc, p_wk, p_kvraw, CC, NN, CC, NKV,
        (size_t)CC * NN, 0, (size_t)NN * NKV);
    gemm_tf32<false, true><<<gp, 256, GEMM_SMEM>>>(
        p_yc, p_wv, p_kvraw + 512, CC, NN, CC, NKV,
        (size_t)CC * NN, 0, (size_t)NN * NKV);

    // 3) sigmoid / exp transforms (+biases), tf32-convert GEMM operands
    transform_kernel<<<BB * NN * 128 / 256, 256>>>(bq, bk, bv);

    // 4) Attention GEMM: [num|den] = eb @ [ekv|ek]
    dim3 ga(NN / 128, NKV / 256, BB);  // (18, 4, 8)
    gemm_tf32<true, false><<<ga, 256, GEMM_SMEM>>>(
        p_eb, p_kv, p_nd, NN, NN, NKV, NKV,
        0, (size_t)NN * NKV, (size_t)NN * NKV);

    // 5) Final epilogue with transpose
    dim3 gf(NN / 32, CC / 32, BB);     // (72, 16, 8)
    final_kernel<<<gf, 256>>>(out);
}

// round 4
// speedup vs baseline: 3.1259x; 1.4444x over previous
#include <cuda_runtime.h>
#include <math.h>
#include <stdint.h>

// Problem constants
#define BB 8
#define CC 512
#define NN 2304          // 48*48
#define NPROJ 1536       // q(512) | interleaved k,v (1024)
#define NKV 1024         // interleaved [ekv|ek] pairs: col 2c=ekv_c, 2c+1=ek_c

// ---------------------------------------------------------------------------
// Scratch (device globals; allocation-free per harness rules)
// ---------------------------------------------------------------------------
__device__ float g_ebT[NN * NN];          // tf32(exp(pos_bias))^T  [j][i]
__device__ float g_xc [BB * CC * NN];     // tf32(x)  [b][c'][i]
__device__ float g_yc [BB * CC * NN];     // tf32(y)
__device__ float g_w  [CC * NPROJ];       // tf32 W^T: [k][n]  n: q_c | k_c,v_c interleaved
__device__ float g_sq [BB * NN * CC];     // sigmoid(q)  [b][i][c]
__device__ float g_kv [BB * NN * NKV];    // tf32 interleaved [b][j][2c|2c+1]

// ---------------------------------------------------------------------------
// Helpers
// ---------------------------------------------------------------------------
__device__ __forceinline__ float f2tf(float x) {
    uint32_t r;
    asm("cvt.rna.tf32.f32 %0, %1;" : "=r"(r) : "f"(x));
    return __uint_as_float(r);
}

__device__ __forceinline__ void mma_tf32(float c[4], const uint32_t a[4],
                                         const uint32_t b[2]) {
    asm volatile(
        "mma.sync.aligned.m16n8k8.row.col.f32.tf32.tf32.f32 "
        "{%0,%1,%2,%3},{%4,%5,%6,%7},{%8,%9},{%0,%1,%2,%3};\n"
        : "+f"(c[0]), "+f"(c[1]), "+f"(c[2]), "+f"(c[3])
        : "r"(a[0]), "r"(a[1]), "r"(a[2]), "r"(a[3]), "r"(b[0]), "r"(b[1]));
}

// ---------------------------------------------------------------------------
// Prep kernels
// ---------------------------------------------------------------------------
__global__ void cvt_kernel(const float* __restrict__ src, float* __restrict__ dst) {
    int idx = blockIdx.x * blockDim.x + threadIdx.x;
    float4 p = ((const float4*)src)[idx];
    float4 o;
    o.x = f2tf(p.x); o.y = f2tf(p.y); o.z = f2tf(p.z); o.w = f2tf(p.w);
    ((float4*)dst)[idx] = o;
}

// Build W^T with q | interleaved(k,v) column layout:
//   g_w[kk][c]        = Wq[c][kk]            c in [0,512)
//   g_w[kk][512+2c]   = Wk[c][kk]
//   g_w[kk][512+2c+1] = Wv[c][kk]
__global__ void cvt_w_kernel(const float* __restrict__ Wq,
                             const float* __restrict__ Wk,
                             const float* __restrict__ Wv) {
    int idx = blockIdx.x * blockDim.x + threadIdx.x;   // over CC*CC
    int c  = idx >> 9;
    int kk = idx & 511;
    float q = Wq[idx], k = Wk[idx], v = Wv[idx];
    g_w[(size_t)kk * NPROJ + c]               = f2tf(q);
    g_w[(size_t)kk * NPROJ + 512 + 2 * c]     = f2tf(k);
    g_w[(size_t)kk * NPROJ + 512 + 2 * c + 1] = f2tf(v);
}

// ebT[j][i] = tf32(exp(pb[i][j]))  -- tiled transpose
__global__ void ebT_kernel(const float* __restrict__ pb) {
    __shared__ float t[32][33];
    const int i0 = blockIdx.x * 32;
    const int j0 = blockIdx.y * 32;
    const int tx = threadIdx.x & 31;
    const int ty = threadIdx.x >> 5;   // 0..7
    #pragma unroll
    for (int r = 0; r < 4; r++) {
        int i = i0 + ty + 8 * r;
        t[ty + 8 * r][tx] = f2tf(__expf(pb[(size_t)i * NN + j0 + tx]));
    }
    __syncthreads();
    #pragma unroll
    for (int r = 0; r < 4; r++) {
        int j = j0 + ty + 8 * r;
        g_ebT[(size_t)j * NN + i0 + tx] = t[tx][ty + 8 * r];
    }
}

// ---------------------------------------------------------------------------
// tf32 GEMM core: BM=128 BN=256 BK=32, 256 thr, warp 64x64, ping-pong smem
// A: [K][M] (K-major), B: [K][N]. smem strides SA/SB ≡ 8 mod 32.
// MODE 0: projection (A = x or y by region; B = g_w; fused sigmoid/exp epilogue)
// MODE 1: attention  (A = ebT; B = g_kv; fused sq*num/den + transpose epilogue)
// ---------------------------------------------------------------------------
#define SA 136
#define SB 264
#define ABUF (32 * SA)           // 4352 floats
#define BBUF (32 * SB)           // 8448 floats
#define GEMM_SMEM ((2 * ABUF + 2 * BBUF) * 4)   // 102400 B

template <int MODE>
__global__ void __launch_bounds__(256)
gemm_tf32(const float* __restrict__ bq, const float* __restrict__ bk,
          const float* __restrict__ bv, float* __restrict__ out) {
    extern __shared__ float sm[];

    const int b  = blockIdx.z;
    const int m0 = blockIdx.x * 128;
    const int n0 = blockIdx.y * 256;
    const int tid = threadIdx.x;

    const float* Ag;
    const float* Bg;
    int K, lda, ldb;
    if (MODE == 0) {
        Ag = ((blockIdx.y < 2) ? g_xc : g_yc) + (size_t)b * CC * NN;
        Bg = g_w;
        K = CC; lda = NN; ldb = NPROJ;
    } else {
        Ag = g_ebT;
        Bg = g_kv + (size_t)b * NN * NKV;
        K = NN; lda = NN; ldb = NKV;
    }

    const int wid = tid >> 5;
    const int mw = (wid & 1) * 64;
    const int nw = (wid >> 1) * 64;
    const int lane = tid & 31;
    const int lq = lane & 3;
    const int lr = lane >> 2;

    float acc[4][8][4];
    #pragma unroll
    for (int i = 0; i < 4; i++)
        #pragma unroll
        for (int j = 0; j < 8; j++)
            #pragma unroll
            for (int l = 0; l < 4; l++) acc[i][j][l] = 0.f;

    float4 ra[4], rb[8];

    auto loadG = [&](int k0) {
        #pragma unroll
        for (int r = 0; r < 4; r++) {
            int v = tid + r * 256;
            int kr = v >> 5, mc = (v & 31) << 2;
            ra[r] = *(const float4*)(Ag + (size_t)(k0 + kr) * lda + m0 + mc);
        }
        #pragma unroll
        for (int r = 0; r < 8; r++) {
            int v = tid + r * 256;
            int kr = v >> 6, nc = (v & 63) << 2;
            rb[r] = *(const float4*)(Bg + (size_t)(k0 + kr) * ldb + n0 + nc);
        }
    };
    auto storeS = [&](int buf) {
        float* As = sm + buf * ABUF;
        float* Bs = sm + 2 * ABUF + buf * BBUF;
        #pragma unroll
        for (int r = 0; r < 4; r++) {
            int v = tid + r * 256;
            int kr = v >> 5, mc = (v & 31) << 2;
            *(float4*)(As + kr * SA + mc) = ra[r];
        }
        #pragma unroll
        for (int r = 0; r < 8; r++) {
            int v = tid + r * 256;
            int kr = v >> 6, nc = (v & 63) << 2;
            *(float4*)(Bs + kr * SB + nc) = rb[r];
        }
    };

    loadG(0);
    storeS(0);
    __syncthreads();

    const int nchunks = K / 32;
    for (int c = 0; c < nchunks; c++) {
        const int cur = c & 1;
        const bool more = (c + 1) < nchunks;
        if (more) loadG((c + 1) * 32);

        const float* As = sm + cur * ABUF;
        const float* Bs = sm + 2 * ABUF + cur * BBUF;
        #pragma unroll
        for (int ka = 0; ka < 4; ka++) {
            uint32_t af[4][4], bf[8][2];
            #pragma unroll
            for (int mi = 0; mi < 4; mi++) {
                int base = (8 * ka + lq) * SA + mw + 16 * mi + lr;
                af[mi][0] = __float_as_uint(As[base]);
                af[mi][1] = __float_as_uint(As[base + 8]);
                af[mi][2] = __float_as_uint(As[base + 4 * SA]);
                af[mi][3] = __float_as_uint(As[base + 4 * SA + 8]);
            }
            #pragma unroll
            for (int ni = 0; ni < 8; ni++) {
                int base = (8 * ka + lq) * SB + nw + 8 * ni + lr;
                bf[ni][0] = __float_as_uint(Bs[base]);
                bf[ni][1] = __float_as_uint(Bs[base + 4 * SB]);
            }
            #pragma unroll
            for (int mi = 0; mi < 4; mi++)
                #pragma unroll
                for (int ni = 0; ni < 8; ni++)
                    mma_tf32(acc[mi][ni], af[mi], bf[ni]);
        }
        __syncthreads();
        if (more) {
            storeS(cur ^ 1);
            __syncthreads();
        }
    }

    // ------------------------------- Epilogues -----------------------------
    if (MODE == 0) {
        if (n0 < 512) {
            // q region: sq = sigmoid(acc + bq)
            float* sq = g_sq + (size_t)b * NN * CC;
            #pragma unroll
            for (int mi = 0; mi < 4; mi++) {
                #pragma unroll
                for (int ni = 0; ni < 8; ni++) {
                    int row = m0 + mw + 16 * mi + lr;
                    int col = n0 + nw + 8 * ni + 2 * lq;
                    float b0 = bq[col], b1 = bq[col + 1];
                    float* a = acc[mi][ni];
                    float2 v0, v1;
                    v0.x = __fdividef(1.f, 1.f + __expf(-(a[0] + b0)));
                    v0.y = __fdividef(1.f, 1.f + __expf(-(a[1] + b1)));
                    v1.x = __fdividef(1.f, 1.f + __expf(-(a[2] + b0)));
                    v1.y = __fdividef(1.f, 1.f + __expf(-(a[3] + b1)));
                    *(float2*)(sq + (size_t)row * CC + col) = v0;
                    *(float2*)(sq + (size_t)(row + 8) * CC + col) = v1;
                }
            }
        } else {
            // kv region: even col = k_c, odd = v_c; write (ekv, ek) interleaved
            float* kv = g_kv + (size_t)b * NN * NKV;
            #pragma unroll
            for (int mi = 0; mi < 4; mi++) {
                #pragma unroll
                for (int ni = 0; ni < 8; ni++) {
                    int row = m0 + mw + 16 * mi + lr;
                    int col = n0 + nw + 8 * ni + 2 * lq - 512;  // even, in kv space
                    int ch = col >> 1;
                    float bkc = bk[ch], bvc = bv[ch];
                    float* a = acc[mi][ni];
                    float e0 = __expf(a[0] + bkc);
                    float e1 = __expf(a[2] + bkc);
                    float2 v0, v1;
                    v0.x = f2tf(e0 * (a[1] + bvc)); v0.y = f2tf(e0);
                    v1.x = f2tf(e1 * (a[3] + bvc)); v1.y = f2tf(e1);
                    *(float2*)(kv + (size_t)row * NKV + col) = v0;
                    *(float2*)(kv + (size_t)(row + 8) * NKV + col) = v1;
                }
            }
        }
    } else {
        // attn: even col = num_c, odd = den_c -> r = sq * num/den,
        // transpose through smem, write out[b][c][i] coalesced.
        __syncthreads();   // done with mainloop smem
        float* so = sm;    // tile [c_local 0..127][m_local 0..127], stride 136
        const float* sq = g_sq + (size_t)b * NN * CC;
        const int gc0 = n0 >> 1;
        #pragma unroll
        for (int mi = 0; mi < 4; mi++) {
            #pragma unroll
            for (int ni = 0; ni < 8; ni++) {
                int rowm = mw + 16 * mi + lr;            // m_local
                int cl = (nw >> 1) + 4 * ni + lq;        // c_local
                int gi = m0 + rowm;
                int gc = gc0 + cl;
                float* a = acc[mi][ni];
                float s0 = sq[(size_t)gi * CC + gc];
                float s1 = sq[(size_t)(gi + 8) * CC + gc];
                so[cl * 136 + rowm]     = s0 * __fdividef(a[0], a[1]);
                so[cl * 136 + rowm + 8] = s1 * __fdividef(a[2], a[3]);
            }
        }
        __syncthreads();
        float* o = out + (size_t)b * CC * NN;
        #pragma unroll
        for (int r = 0; r < 16; r++) {
            int v = tid + r * 256;
            int cl = v >> 5, m4 = (v & 31) << 2;
            float4 val = *(float4*)(so + cl * 136 + m4);
            *(float4*)(o + (size_t)(gc0 + cl) * NN + m0 + m4) = val;
        }
    }
}

// ---------------------------------------------------------------------------
// Launch.  Order matters for ncu (-s 5 => attn GEMM is launch index 5):
//   0: cvt_x  1: cvt_y  2: cvt_w  3: ebT  4: proj  5: attn
// ---------------------------------------------------------------------------
extern "C" void kernel_launch(void* const* d_in, const int* in_sizes, int n_in,
                              void* d_out, int out_size) {
    const float* x  = (const float*)d_in[0];
    const float* y  = (const float*)d_in[1];
    const float* Wq = (const float*)d_in[2];
    const float* bq = (const float*)d_in[3];
    const float* Wk = (const float*)d_in[4];
    const float* bk = (const float*)d_in[5];
    const float* Wv = (const float*)d_in[6];
    const float* bv = (const float*)d_in[7];
    const float* pb = (const float*)d_in[8];
    float* out = (float*)d_out;

    static bool attr_done = false;
    if (!attr_done) {
        cudaFuncSetAttribute(gemm_tf32<0>,
                             cudaFuncAttributeMaxDynamicSharedMemorySize, GEMM_SMEM);
        cudaFuncSetAttribute(gemm_tf32<1>,
                             cudaFuncAttributeMaxDynamicSharedMemorySize, GEMM_SMEM);
        attr_done = true;
    }

    float *p_xc, *p_yc;
    cudaGetSymbolAddress((void**)&p_xc, g_xc);
    cudaGetSymbolAddress((void**)&p_yc, g_yc);

    // 0,1) tf32 conversions of x, y
    cvt_kernel<<<BB * CC * NN / 4 / 256, 256>>>(x, p_xc);
    cvt_kernel<<<BB * CC * NN / 4 / 256, 256>>>(y, p_yc);
    // 2) W^T interleaved
    cvt_w_kernel<<<CC * CC / 256, 256>>>(Wq, Wk, Wv);
    // 3) ebT
    {
        dim3 g(NN / 32, NN / 32);
        ebT_kernel<<<g, 256>>>(pb);
    }
    // 4) fused projection GEMM -> g_sq, g_kv
    {
        dim3 g(NN / 128, NPROJ / 256, BB);   // (18, 6, 8)
        gemm_tf32<0><<<g, 256, GEMM_SMEM>>>(bq, bk, bv, nullptr);
    }
    // 5) attention GEMM + final fused epilogue -> out
    {
        dim3 g(NN / 128, NKV / 256, BB);     // (18, 4, 8)
        gemm_tf32<1><<<g, 256, GEMM_SMEM>>>(bq, bk, bv, out);
    }
}

// round 6
// speedup vs baseline: 5.5887x; 1.7879x over previous
#include <cuda_runtime.h>
#include <cuda_fp16.h>
#include <math.h>
#include <stdint.h>

// Problem constants
#define BB 8
#define CC 512
#define NN 2304          // 48*48
#define NPROJ 1536       // q(512) | interleaved k,v (1024)
#define NKV 1024         // interleaved pairs: col 2c=ekv_c, 2c+1=ek_c
#define KPH 256          // half2 K-rows for projection (CC/2)
#define KAH 1152         // half2 K-rows for attention (NN/2)

// ---------------------------------------------------------------------------
// Scratch (device globals; allocation-free per harness rules)
// g_xh/g_yh: half2 (x[2cp][i], x[2cp+1][i])  layout [b][cp][i]
// g_wh:      half2 (W(n)[2kp], W(n)[2kp+1])  layout [kp][n], n = q | interleaved k,v
// g_ebh:     half2 (eb[i][2jp], eb[i][2jp+1]) layout [jp][i]  (exp + transpose)
// g_kv:      fp32 [b][j][c2]  (even c2 = ek*v, odd = ek)
// g_kvh:     half2 (kv[2jp][c2], kv[2jp+1][c2]) layout [b][jp][c2]
// ---------------------------------------------------------------------------
__device__ uint32_t g_xh [BB * KPH * NN];
__device__ uint32_t g_yh [BB * KPH * NN];
__device__ uint32_t g_wh [KPH * NPROJ];
__device__ uint32_t g_ebh[KAH * NN];
__device__ float    g_sq [BB * NN * CC];
__device__ float    g_kv [BB * NN * NKV];
__device__ uint32_t g_kvh[BB * KAH * NKV];

// ---------------------------------------------------------------------------
// Helpers
// ---------------------------------------------------------------------------
__device__ __forceinline__ uint32_t packh2(float lo, float hi) {
    __half2 h = __floats2half2_rn(lo, hi);   // .x = lo (low 16 bits) = even-k
    return *reinterpret_cast<uint32_t*>(&h);
}

__device__ __forceinline__ void mma_f16(float c[4], const uint32_t a[4],
                                        const uint32_t b[2]) {
    asm volatile(
        "mma.sync.aligned.m16n8k16.row.col.f32.f16.f16.f32 "
        "{%0,%1,%2,%3},{%4,%5,%6,%7},{%8,%9},{%0,%1,%2,%3};\n"
        : "+f"(c[0]), "+f"(c[1]), "+f"(c[2]), "+f"(c[3])
        : "r"(a[0]), "r"(a[1]), "r"(a[2]), "r"(a[3]), "r"(b[0]), "r"(b[1]));
}

// ---------------------------------------------------------------------------
// prep_all: one kernel, 4 block ranges
//   [0,4608)      xh     [4608,9216)  yh
//   [9216,10752)  wh     [10752,13344) ebh (exp + transpose)
// ---------------------------------------------------------------------------
#define PB_XY 4608
#define PB_W  1536
#define PB_EB 2592
#define PREP_BLOCKS (2 * PB_XY + PB_W + PB_EB)   // 13344

__global__ void __launch_bounds__(256)
prep_all(const float* __restrict__ x, const float* __restrict__ y,
         const float* __restrict__ Wq, const float* __restrict__ Wk,
         const float* __restrict__ Wv, const float* __restrict__ pb) {
    const int tid = threadIdx.x;
    const int blk = blockIdx.x;

    if (blk < 2 * PB_XY) {
        // xh / yh: half2 pack over channel pairs
        const bool isx = blk < PB_XY;
        const float* src = isx ? x : y;
        uint32_t* dst = isx ? g_xh : g_yh;
        int v = (isx ? blk : blk - PB_XY) * 256 + tid;   // over BB*256*576
        int b  = v / (256 * 576);
        int r  = v % (256 * 576);
        int cp = r / 576;
        int i  = (r % 576) * 4;
        const float* base = src + ((size_t)(b * CC + 2 * cp)) * NN + i;
        float4 lo = *(const float4*)(base);
        float4 hi = *(const float4*)(base + NN);
        uint4 o;
        o.x = packh2(lo.x, hi.x); o.y = packh2(lo.y, hi.y);
        o.z = packh2(lo.z, hi.z); o.w = packh2(lo.w, hi.w);
        *(uint4*)(dst + ((size_t)(b * KPH + cp)) * NN + i) = o;
    } else if (blk < 2 * PB_XY + PB_W) {
        // wh: [kp][n] half2, n = q(512) | kv-interleaved(1024)
        int v = (blk - 2 * PB_XY) * 256 + tid;   // over 256*1536
        int kp = v / NPROJ;
        int n  = v % NPROJ;
        const float* W;
        int c;
        if (n < 512) { W = Wq; c = n; }
        else {
            int m = n - 512;
            c = m >> 1;
            W = (m & 1) ? Wv : Wk;
        }
        float a = W[(size_t)c * CC + 2 * kp];
        float bv_ = W[(size_t)c * CC + 2 * kp + 1];
        g_wh[(size_t)kp * NPROJ + n] = packh2(a, bv_);
    } else {
        // ebh: [jp][i] = half2(exp(pb[i][2jp]), exp(pb[i][2jp+1]))
        __shared__ float s[32][65];
        int t = blk - (2 * PB_XY + PB_W);
        int ti = t % 72, tj = t / 72;
        int i0 = ti * 32, j0 = tj * 64;
        int il = tid >> 3;
        int jq = (tid & 7) * 8;
        const float* p = pb + (size_t)(i0 + il) * NN + j0 + jq;
        float4 p0 = *(const float4*)(p);
        float4 p1 = *(const float4*)(p + 4);
        s[il][jq + 0] = __expf(p0.x); s[il][jq + 1] = __expf(p0.y);
        s[il][jq + 2] = __expf(p0.z); s[il][jq + 3] = __expf(p0.w);
        s[il][jq + 4] = __expf(p1.x); s[il][jq + 5] = __expf(p1.y);
        s[il][jq + 6] = __expf(p1.z); s[il][jq + 7] = __expf(p1.w);
        __syncthreads();
        #pragma unroll
        for (int k = 0; k < 4; k++) {
            int idx = tid + k * 256;
            int jpl = idx >> 5;
            int i_l = idx & 31;
            g_ebh[(size_t)(tj * 32 + jpl) * NN + i0 + i_l] =
                packh2(s[i_l][2 * jpl], s[i_l][2 * jpl + 1]);
        }
    }
}

// ---------------------------------------------------------------------------
// kv_repack: fp32 [b][j][c2] -> half2 [b][jp][c2] packed over j pairs
// ---------------------------------------------------------------------------
__global__ void __launch_bounds__(256)
kv_repack() {
    int v = blockIdx.x * 256 + threadIdx.x;   // over BB*1152*256
    int b  = v / (KAH * 256);
    int r  = v % (KAH * 256);
    int jp = r / 256;
    int c4 = (r % 256) * 4;
    const float* base = g_kv + ((size_t)(b * NN + 2 * jp)) * NKV + c4;
    float4 lo = *(const float4*)(base);
    float4 hi = *(const float4*)(base + NKV);
    uint4 o;
    o.x = packh2(lo.x, hi.x); o.y = packh2(lo.y, hi.y);
    o.z = packh2(lo.z, hi.z); o.w = packh2(lo.w, hi.w);
    *(uint4*)(g_kvh + ((size_t)(b * KAH + jp)) * NKV + c4) = o;
}

// ---------------------------------------------------------------------------
// fp16 GEMM core: BM=128 BN=256, K-chunk = 32 half2-rows (64 fp32-equiv K),
// 256 thr, warp 64x64, ping-pong smem.  Elements are half2 (uint32).
// MODE 0: projection (A = xh/yh; B = wh; epilogue sigmoid-q / ekv-ek)
// MODE 1: attention  (A = ebh; B = kvh; epilogue sq*num/den + transpose out)
// ---------------------------------------------------------------------------
#define SAH 136
#define SBH 264
#define ABUFH (32 * SAH)          // 4352 u32
#define BBUFH (32 * SBH)          // 8448 u32
#define GEMM_SMEM ((2 * ABUFH + 2 * BBUFH) * 4)   // 102400 B

template <int MODE>
__global__ void __launch_bounds__(256)
gemm_f16(const float* __restrict__ bq, const float* __restrict__ bk,
         const float* __restrict__ bv, float* __restrict__ out) {
    extern __shared__ uint32_t smu[];

    const int b  = blockIdx.z;
    const int m0 = blockIdx.x * 128;
    const int n0 = blockIdx.y * 256;
    const int tid = threadIdx.x;

    const uint32_t* Ag;
    const uint32_t* Bg;
    int ldaH, ldbH, nch;
    if (MODE == 0) {
        Ag = ((blockIdx.y < 2) ? g_xh : g_yh) + (size_t)b * KPH * NN;
        Bg = g_wh;
        ldaH = NN; ldbH = NPROJ; nch = KPH / 32;     // 8
    } else {
        Ag = g_ebh;
        Bg = g_kvh + (size_t)b * KAH * NKV;
        ldaH = NN; ldbH = NKV; nch = KAH / 32;       // 36
    }

    const int wid = tid >> 5;
    const int mw = (wid & 1) * 64;
    const int nw = (wid >> 1) * 64;
    const int lane = tid & 31;
    const int lq = lane & 3;
    const int lr = lane >> 2;

    float acc[4][8][4];
    #pragma unroll
    for (int i = 0; i < 4; i++)
        #pragma unroll
        for (int j = 0; j < 8; j++)
            #pragma unroll
            for (int l = 0; l < 4; l++) acc[i][j][l] = 0.f;

    uint4 ra[4], rb[8];

    auto loadG = [&](int ck) {
        #pragma unroll
        for (int r = 0; r < 4; r++) {
            int v = tid + r * 256;
            int kr = v >> 5, ic = (v & 31) << 2;
            ra[r] = *(const uint4*)(Ag + (size_t)(ck * 32 + kr) * ldaH + m0 + ic);
        }
        #pragma unroll
        for (int r = 0; r < 8; r++) {
            int v = tid + r * 256;
            int kr = v >> 6, nc = (v & 63) << 2;
            rb[r] = *(const uint4*)(Bg + (size_t)(ck * 32 + kr) * ldbH + n0 + nc);
        }
    };
    auto storeS = [&](int buf) {
        uint32_t* As = smu + buf * ABUFH;
        uint32_t* Bs = smu + 2 * ABUFH + buf * BBUFH;
        #pragma unroll
        for (int r = 0; r < 4; r++) {
            int v = tid + r * 256;
            int kr = v >> 5, ic = (v & 31) << 2;
            *(uint4*)(As + kr * SAH + ic) = ra[r];
        }
        #pragma unroll
        for (int r = 0; r < 8; r++) {
            int v = tid + r * 256;
            int kr = v >> 6, nc = (v & 63) << 2;
            *(uint4*)(Bs + kr * SBH + nc) = rb[r];
        }
    };

    loadG(0);
    storeS(0);
    __syncthreads();

    for (int c = 0; c < nch; c++) {
        const int cur = c & 1;
        const bool more = (c + 1) < nch;
        if (more) loadG(c + 1);

        const uint32_t* As = smu + cur * ABUFH;
        const uint32_t* Bs = smu + 2 * ABUFH + cur * BBUFH;
        #pragma unroll
        for (int ka = 0; ka < 4; ka++) {
            uint32_t af[4][4], bf[8][2];
            const int kp = 8 * ka + lq;
            #pragma unroll
            for (int mi = 0; mi < 4; mi++) {
                int base = kp * SAH + mw + 16 * mi + lr;
                af[mi][0] = As[base];
                af[mi][1] = As[base + 8];
                af[mi][2] = As[base + 4 * SAH];
                af[mi][3] = As[base + 4 * SAH + 8];
            }
            #pragma unroll
            for (int ni = 0; ni < 8; ni++) {
                int base = kp * SBH + nw + 8 * ni + lr;
                bf[ni][0] = Bs[base];
                bf[ni][1] = Bs[base + 4 * SBH];
            }
            #pragma unroll
            for (int mi = 0; mi < 4; mi++)
                #pragma unroll
                for (int ni = 0; ni < 8; ni++)
                    mma_f16(acc[mi][ni], af[mi], bf[ni]);
        }
        __syncthreads();
        if (more) {
            storeS(cur ^ 1);
            __syncthreads();
        }
    }

    // ------------------------------- Epilogues -----------------------------
    if (MODE == 0) {
        if (n0 < 512) {
            // q region: sq = sigmoid(acc + bq)
            float* sq = g_sq + (size_t)b * NN * CC;
            #pragma unroll
            for (int mi = 0; mi < 4; mi++) {
                #pragma unroll
                for (int ni = 0; ni < 8; ni++) {
                    int row = m0 + mw + 16 * mi + lr;
                    int col = n0 + nw + 8 * ni + 2 * lq;
                    float b0 = bq[col], b1 = bq[col + 1];
                    float* a = acc[mi][ni];
                    float2 v0, v1;
                    v0.x = __fdividef(1.f, 1.f + __expf(-(a[0] + b0)));
                    v0.y = __fdividef(1.f, 1.f + __expf(-(a[1] + b1)));
                    v1.x = __fdividef(1.f, 1.f + __expf(-(a[2] + b0)));
                    v1.y = __fdividef(1.f, 1.f + __expf(-(a[3] + b1)));
                    *(float2*)(sq + (size_t)row * CC + col) = v0;
                    *(float2*)(sq + (size_t)(row + 8) * CC + col) = v1;
                }
            }
        } else {
            // kv region: even frag col = k_c, odd = v_c; write (ekv, ek) fp32
            float* kv = g_kv + (size_t)b * NN * NKV;
            #pragma unroll
            for (int mi = 0; mi < 4; mi++) {
                #pragma unroll
                for (int ni = 0; ni < 8; ni++) {
                    int row = m0 + mw + 16 * mi + lr;            // j
                    int col = n0 + nw + 8 * ni + 2 * lq - 512;   // even = 2*ch
                    int ch = col >> 1;
                    float bkc = bk[ch], bvc = bv[ch];
                    float* a = acc[mi][ni];
                    float e0 = __expf(a[0] + bkc);
                    float e1 = __expf(a[2] + bkc);
                    float2 v0, v1;
                    v0.x = e0 * (a[1] + bvc); v0.y = e0;
                    v1.x = e1 * (a[3] + bvc); v1.y = e1;
                    *(float2*)(kv + (size_t)row * NKV + col) = v0;
                    *(float2*)(kv + (size_t)(row + 8) * NKV + col) = v1;
                }
            }
        }
    } else {
        // attn: even col = num, odd = den -> sq * num/den -> transpose -> out
        __syncthreads();
        float* so = (float*)smu;   // [c_local 0..127][m_local 0..127] stride 136
        const float* sq = g_sq + (size_t)b * NN * CC;
        const int gc0 = n0 >> 1;
        #pragma unroll
        for (int mi = 0; mi < 4; mi++) {
            #pragma unroll
            for (int ni = 0; ni < 8; ni++) {
                int rowm = mw + 16 * mi + lr;
                int cl = (nw >> 1) + 4 * ni + lq;
                int gi = m0 + rowm;
                int gc = gc0 + cl;
                float* a = acc[mi][ni];
                float s0 = sq[(size_t)gi * CC + gc];
                float s1 = sq[(size_t)(gi + 8) * CC + gc];
                so[cl * 136 + rowm]     = s0 * __fdividef(a[0], a[1]);
                so[cl * 136 + rowm + 8] = s1 * __fdividef(a[2], a[3]);
            }
        }
        __syncthreads();
        float* o = out + (size_t)b * CC * NN;
        #pragma unroll
        for (int r2 = 0; r2 < 16; r2++) {
            int v = tid + r2 * 256;
            int cl = v >> 5, m4 = (v & 31) << 2;
            float4 val = *(float4*)(so + cl * 136 + m4);
            *(float4*)(o + (size_t)(gc0 + cl) * NN + m0 + m4) = val;
        }
    }
}

// ---------------------------------------------------------------------------
// Launch.  Order: 0 prep_all, 1 proj, 2 kv_repack, 3 attn (profiled index)
// ---------------------------------------------------------------------------
extern "C" void kernel_launch(void* const* d_in, const int* in_sizes, int n_in,
                              void* d_out, int out_size) {
    const float* x  = (const float*)d_in[0];
    const float* y  = (const float*)d_in[1];
    const float* Wq = (const float*)d_in[2];
    const float* bq = (const float*)d_in[3];
    const float* Wk = (const float*)d_in[4];
    const float* bk = (const float*)d_in[5];
    const float* Wv = (const float*)d_in[6];
    const float* bv = (const float*)d_in[7];
    const float* pb = (const float*)d_in[8];
    float* out = (float*)d_out;

    static bool attr_done = false;
    if (!attr_done) {
        cudaFuncSetAttribute(gemm_f16<0>,
                             cudaFuncAttributeMaxDynamicSharedMemorySize, GEMM_SMEM);
        cudaFuncSetAttribute(gemm_f16<1>,
                             cudaFuncAttributeMaxDynamicSharedMemorySize, GEMM_SMEM);
        attr_done = true;
    }

    // 0) all operand prep in one kernel
    prep_all<<<PREP_BLOCKS, 256>>>(x, y, Wq, Wk, Wv, pb);

    // 1) fused projection GEMM -> g_sq (fp32), g_kv (fp32)
    {
        dim3 g(NN / 128, NPROJ / 256, BB);   // (18, 6, 8)
        gemm_f16<0><<<g, 256, GEMM_SMEM>>>(bq, bk, bv, nullptr);
    }

    // 2) pack kv j-pairs to half2
    kv_repack<<<BB * KAH * 256 / 256, 256>>>();

    // 3) attention GEMM + fused final epilogue -> out
    {
        dim3 g(NN / 128, NKV / 256, BB);     // (18, 4, 8)
        gemm_f16<1><<<g, 256, GEMM_SMEM>>>(bq, bk, bv, out);
    }
}

// round 7
// speedup vs baseline: 5.8753x; 1.0513x over previous
#include <cuda_runtime.h>
#include <cuda_fp16.h>
#include <math.h>
#include <stdint.h>

// Problem constants
#define BB 8
#define CC 512
#define NN 2304          // 48*48
#define NPROJ 1536       // q(512) | interleaved k,v (1024)
#define NKV 1024         // interleaved pairs: col 2c=ekv_c, 2c+1=ek_c
#define KPH 256          // half2 K-rows for projection (CC/2)
#define KAH 1152         // half2 K-rows for attention (NN/2)

// ---------------------------------------------------------------------------
// Scratch (device globals; allocation-free per harness rules)
// ---------------------------------------------------------------------------
__device__ uint32_t g_xh [BB * KPH * NN];    // half2(x[2cp][i], x[2cp+1][i])
__device__ uint32_t g_yh [BB * KPH * NN];
__device__ uint32_t g_wh [KPH * NPROJ];      // half2 W^T, n = q | k,v interleaved
__device__ uint32_t g_ebh[KAH * NN];         // half2(eb[i][2jp], eb[i][2jp+1]) [jp][i]
__device__ float    g_sq [BB * NN * CC];     // sigmoid(q) [b][i][c]
__device__ float    g_kv [BB * NN * NKV];    // fp32 [b][j][c2]
__device__ uint32_t g_kvh[BB * KAH * NKV];   // half2 over j-pairs [b][jp][c2]

// ---------------------------------------------------------------------------
// Helpers
// ---------------------------------------------------------------------------
__device__ __forceinline__ uint32_t packh2(float lo, float hi) {
    __half2 h = __floats2half2_rn(lo, hi);
    return *reinterpret_cast<uint32_t*>(&h);
}

__device__ __forceinline__ void mma_f16(float c[4], const uint32_t a[4],
                                        const uint32_t b[2]) {
    asm volatile(
        "mma.sync.aligned.m16n8k16.row.col.f32.f16.f16.f32 "
        "{%0,%1,%2,%3},{%4,%5,%6,%7},{%8,%9},{%0,%1,%2,%3};\n"
        : "+f"(c[0]), "+f"(c[1]), "+f"(c[2]), "+f"(c[3])
        : "r"(a[0]), "r"(a[1]), "r"(a[2]), "r"(a[3]), "r"(b[0]), "r"(b[1]));
}

__device__ __forceinline__ uint32_t smem_u32(const void* p) {
    uint32_t a;
    asm("{ .reg .u64 t; cvta.to.shared.u64 t, %1; cvt.u32.u64 %0, t; }"
        : "=r"(a) : "l"(p));
    return a;
}

__device__ __forceinline__ void cp16(uint32_t saddr, const void* gptr) {
    asm volatile("cp.async.cg.shared.global [%0], [%1], 16;"
                 :: "r"(saddr), "l"(gptr));
}
#define CP_COMMIT() asm volatile("cp.async.commit_group;" ::: "memory")
#define CP_WAIT(n)  asm volatile("cp.async.wait_group %0;" :: "n"(n) : "memory")

// ---------------------------------------------------------------------------
// prep_all: one kernel, 4 block ranges
// ---------------------------------------------------------------------------
#define PB_XY 4608
#define PB_W  1536
#define PB_EB 2592
#define PREP_BLOCKS (2 * PB_XY + PB_W + PB_EB)   // 13344

__global__ void __launch_bounds__(256)
prep_all(const float* __restrict__ x, const float* __restrict__ y,
         const float* __restrict__ Wq, const float* __restrict__ Wk,
         const float* __restrict__ Wv, const float* __restrict__ pb) {
    const int tid = threadIdx.x;
    const int blk = blockIdx.x;

    if (blk < 2 * PB_XY) {
        const bool isx = blk < PB_XY;
        const float* src = isx ? x : y;
        uint32_t* dst = isx ? g_xh : g_yh;
        int v = (isx ? blk : blk - PB_XY) * 256 + tid;
        int b  = v / (256 * 576);
        int r  = v % (256 * 576);
        int cp = r / 576;
        int i  = (r % 576) * 4;
        const float* base = src + ((size_t)(b * CC + 2 * cp)) * NN + i;
        float4 lo = *(const float4*)(base);
        float4 hi = *(const float4*)(base + NN);
        uint4 o;
        o.x = packh2(lo.x, hi.x); o.y = packh2(lo.y, hi.y);
        o.z = packh2(lo.z, hi.z); o.w = packh2(lo.w, hi.w);
        *(uint4*)(dst + ((size_t)(b * KPH + cp)) * NN + i) = o;
    } else if (blk < 2 * PB_XY + PB_W) {
        int v = (blk - 2 * PB_XY) * 256 + tid;
        int kp = v / NPROJ;
        int n  = v % NPROJ;
        const float* W;
        int c;
        if (n < 512) { W = Wq; c = n; }
        else {
            int m = n - 512;
            c = m >> 1;
            W = (m & 1) ? Wv : Wk;
        }
        float a = W[(size_t)c * CC + 2 * kp];
        float bv_ = W[(size_t)c * CC + 2 * kp + 1];
        g_wh[(size_t)kp * NPROJ + n] = packh2(a, bv_);
    } else {
        __shared__ float s[32][65];
        int t = blk - (2 * PB_XY + PB_W);
        int ti = t % 72, tj = t / 72;
        int i0 = ti * 32, j0 = tj * 64;
        int il = tid >> 3;
        int jq = (tid & 7) * 8;
        const float* p = pb + (size_t)(i0 + il) * NN + j0 + jq;
        float4 p0 = *(const float4*)(p);
        float4 p1 = *(const float4*)(p + 4);
        s[il][jq + 0] = __expf(p0.x); s[il][jq + 1] = __expf(p0.y);
        s[il][jq + 2] = __expf(p0.z); s[il][jq + 3] = __expf(p0.w);
        s[il][jq + 4] = __expf(p1.x); s[il][jq + 5] = __expf(p1.y);
        s[il][jq + 6] = __expf(p1.z); s[il][jq + 7] = __expf(p1.w);
        __syncthreads();
        #pragma unroll
        for (int k = 0; k < 4; k++) {
            int idx = tid + k * 256;
            int jpl = idx >> 5;
            int i_l = idx & 31;
            g_ebh[(size_t)(tj * 32 + jpl) * NN + i0 + i_l] =
                packh2(s[i_l][2 * jpl], s[i_l][2 * jpl + 1]);
        }
    }
}

// ---------------------------------------------------------------------------
// kv_repack: fp32 [b][j][c2] -> half2 [b][jp][c2] packed over j pairs
// ---------------------------------------------------------------------------
__global__ void __launch_bounds__(256)
kv_repack() {
    int v = blockIdx.x * 256 + threadIdx.x;
    int b  = v / (KAH * 256);
    int r  = v % (KAH * 256);
    int jp = r / 256;
    int c4 = (r % 256) * 4;
    const float* base = g_kv + ((size_t)(b * NN + 2 * jp)) * NKV + c4;
    float4 lo = *(const float4*)(base);
    float4 hi = *(const float4*)(base + NKV);
    uint4 o;
    o.x = packh2(lo.x, hi.x); o.y = packh2(lo.y, hi.y);
    o.z = packh2(lo.z, hi.z); o.w = packh2(lo.w, hi.w);
    *(uint4*)(g_kvh + ((size_t)(b * KAH + jp)) * NKV + c4) = o;
}

// ---------------------------------------------------------------------------
// fp16 GEMM core: BM=128 BN=256, K-chunk = 32 half2-rows, 256 thr,
// warp 64x64, 4-stage cp.async ring, 1 sync per chunk.
// MODE 0: projection;  MODE 1: attention (fused final epilogue)
// ---------------------------------------------------------------------------
#define SAH 136
#define SBH 264
#define ABUFH (32 * SAH)          // 4352 u32
#define BBUFH (32 * SBH)          // 8448 u32
#define STG 4
#define GEMM_SMEM (STG * (ABUFH + BBUFH) * 4)   // 204800 B

template <int MODE>
__global__ void __launch_bounds__(256)
gemm_f16(const float* __restrict__ bq, const float* __restrict__ bk,
         const float* __restrict__ bv, float* __restrict__ out) {
    extern __shared__ uint32_t smu[];
    const uint32_t smb = smem_u32(smu);

    const int b  = blockIdx.z;
    const int m0 = blockIdx.x * 128;
    const int n0 = blockIdx.y * 256;
    const int tid = threadIdx.x;

    const uint32_t* Ag;
    const uint32_t* Bg;
    int ldaH, ldbH, nch;
    if (MODE == 0) {
        Ag = ((blockIdx.y < 2) ? g_xh : g_yh) + (size_t)b * KPH * NN;
        Bg = g_wh;
        ldaH = NN; ldbH = NPROJ; nch = KPH / 32;     // 8
    } else {
        Ag = g_ebh;
        Bg = g_kvh + (size_t)b * KAH * NKV;
        ldaH = NN; ldbH = NKV; nch = KAH / 32;       // 36
    }

    const int wid = tid >> 5;
    const int mw = (wid & 1) * 64;
    const int nw = (wid >> 1) * 64;
    const int lane = tid & 31;
    const int lq = lane & 3;
    const int lr = lane >> 2;

    // Per-thread cp.async source/dest precompute
    const int a_kr = tid >> 5, a_ic = (tid & 31) << 2;          // A: 4 rows apart
    const int b_kr = tid >> 6, b_nc = (tid & 63) << 2;          // B: 4 rows apart

    auto loadAsync = [&](int ck, int buf) {
        const uint32_t sA = smb + (buf * ABUFH) * 4;
        const uint32_t sB = smb + (STG * ABUFH + buf * BBUFH) * 4;
        #pragma unroll
        for (int r = 0; r < 4; r++) {
            int kr = a_kr + r * 8;
            cp16(sA + (kr * SAH + a_ic) * 4,
                 Ag + (size_t)(ck * 32 + kr) * ldaH + m0 + a_ic);
        }
        #pragma unroll
        for (int r = 0; r < 8; r++) {
            int kr = b_kr + r * 4;
            cp16(sB + (kr * SBH + b_nc) * 4,
                 Bg + (size_t)(ck * 32 + kr) * ldbH + n0 + b_nc);
        }
    };

    float acc[4][8][4];
    #pragma unroll
    for (int i = 0; i < 4; i++)
        #pragma unroll
        for (int j = 0; j < 8; j++)
            #pragma unroll
            for (int l = 0; l < 4; l++) acc[i][j][l] = 0.f;

    // Prologue: stages 0..STG-2 in flight
    #pragma unroll
    for (int s = 0; s < STG - 1; s++) {
        loadAsync(s, s);
        CP_COMMIT();
    }

    for (int c = 0; c < nch; c++) {
        CP_WAIT(STG - 2);          // group c complete
        __syncthreads();           // visible to all; all readers of buf (c-1)%STG done
        if (c + STG - 1 < nch) loadAsync(c + STG - 1, (c + STG - 1) & (STG - 1));
        CP_COMMIT();               // keep group accounting uniform

        const uint32_t* As = smu + (c & (STG - 1)) * ABUFH;
        const uint32_t* Bs = smu + STG * ABUFH + (c & (STG - 1)) * BBUFH;
        #pragma unroll
        for (int ka = 0; ka < 4; ka++) {
            uint32_t af[4][4], bf[8][2];
            const int kp = 8 * ka + lq;
            #pragma unroll
            for (int mi = 0; mi < 4; mi++) {
                int base = kp * SAH + mw + 16 * mi + lr;
                af[mi][0] = As[base];
                af[mi][1] = As[base + 8];
                af[mi][2] = As[base + 4 * SAH];
                af[mi][3] = As[base + 4 * SAH + 8];
            }
            #pragma unroll
            for (int ni = 0; ni < 8; ni++) {
                int base = kp * SBH + nw + 8 * ni + lr;
                bf[ni][0] = Bs[base];
                bf[ni][1] = Bs[base + 4 * SBH];
            }
            #pragma unroll
            for (int mi = 0; mi < 4; mi++)
                #pragma unroll
                for (int ni = 0; ni < 8; ni++)
                    mma_f16(acc[mi][ni], af[mi], bf[ni]);
        }
    }

    // ------------------------------- Epilogues -----------------------------
    if (MODE == 0) {
        if (n0 < 512) {
            float* sq = g_sq + (size_t)b * NN * CC;
            #pragma unroll
            for (int mi = 0; mi < 4; mi++) {
                #pragma unroll
                for (int ni = 0; ni < 8; ni++) {
                    int row = m0 + mw + 16 * mi + lr;
                    int col = n0 + nw + 8 * ni + 2 * lq;
                    float b0 = bq[col], b1 = bq[col + 1];
                    float* a = acc[mi][ni];
                    float2 v0, v1;
                    v0.x = __fdividef(1.f, 1.f + __expf(-(a[0] + b0)));
                    v0.y = __fdividef(1.f, 1.f + __expf(-(a[1] + b1)));
                    v1.x = __fdividef(1.f, 1.f + __expf(-(a[2] + b0)));
                    v1.y = __fdividef(1.f, 1.f + __expf(-(a[3] + b1)));
                    *(float2*)(sq + (size_t)row * CC + col) = v0;
                    *(float2*)(sq + (size_t)(row + 8) * CC + col) = v1;
                }
            }
        } else {
            float* kv = g_kv + (size_t)b * NN * NKV;
            #pragma unroll
            for (int mi = 0; mi < 4; mi++) {
                #pragma unroll
                for (int ni = 0; ni < 8; ni++) {
                    int row = m0 + mw + 16 * mi + lr;
                    int col = n0 + nw + 8 * ni + 2 * lq - 512;
                    int ch = col >> 1;
                    float bkc = bk[ch], bvc = bv[ch];
                    float* a = acc[mi][ni];
                    float e0 = __expf(a[0] + bkc);
                    float e1 = __expf(a[2] + bkc);
                    float2 v0, v1;
                    v0.x = e0 * (a[1] + bvc); v0.y = e0;
                    v1.x = e1 * (a[3] + bvc); v1.y = e1;
                    *(float2*)(kv + (size_t)row * NKV + col) = v0;
                    *(float2*)(kv + (size_t)(row + 8) * NKV + col) = v1;
                }
            }
        }
    } else {
        __syncthreads();
        float* so = (float*)smu;   // [c_local][m_local] stride 136
        const float* sq = g_sq + (size_t)b * NN * CC;
        const int gc0 = n0 >> 1;
        #pragma unroll
        for (int mi = 0; mi < 4; mi++) {
            #pragma unroll
            for (int ni = 0; ni < 8; ni++) {
                int rowm = mw + 16 * mi + lr;
                int cl = (nw >> 1) + 4 * ni + lq;
                int gi = m0 + rowm;
                int gc = gc0 + cl;
                float* a = acc[mi][ni];
                float s0 = sq[(size_t)gi * CC + gc];
                float s1 = sq[(size_t)(gi + 8) * CC + gc];
                so[cl * 136 + rowm]     = s0 * __fdividef(a[0], a[1]);
                so[cl * 136 + rowm + 8] = s1 * __fdividef(a[2], a[3]);
            }
        }
        __syncthreads();
        float* o = out + (size_t)b * CC * NN;
        #pragma unroll
        for (int r2 = 0; r2 < 16; r2++) {
            int v = tid + r2 * 256;
            int cl = v >> 5, m4 = (v & 31) << 2;
            float4 val = *(float4*)(so + cl * 136 + m4);
            *(float4*)(o + (size_t)(gc0 + cl) * NN + m0 + m4) = val;
        }
    }
}

// ---------------------------------------------------------------------------
// Launch.  Order: 0 prep_all, 1 proj, 2 kv_repack, 3 attn
// ---------------------------------------------------------------------------
extern "C" void kernel_launch(void* const* d_in, const int* in_sizes, int n_in,
                              void* d_out, int out_size) {
    const float* x  = (const float*)d_in[0];
    const float* y  = (const float*)d_in[1];
    const float* Wq = (const float*)d_in[2];
    const float* bq = (const float*)d_in[3];
    const float* Wk = (const float*)d_in[4];
    const float* bk = (const float*)d_in[5];
    const float* Wv = (const float*)d_in[6];
    const float* bv = (const float*)d_in[7];
    const float* pb = (const float*)d_in[8];
    float* out = (float*)d_out;

    static bool attr_done = false;
    if (!attr_done) {
        cudaFuncSetAttribute(gemm_f16<0>,
                             cudaFuncAttributeMaxDynamicSharedMemorySize, GEMM_SMEM);
        cudaFuncSetAttribute(gemm_f16<1>,
                             cudaFuncAttributeMaxDynamicSharedMemorySize, GEMM_SMEM);
        attr_done = true;
    }

    // 0) all operand prep in one kernel
    prep_all<<<PREP_BLOCKS, 256>>>(x, y, Wq, Wk, Wv, pb);

    // 1) fused projection GEMM -> g_sq (fp32), g_kv (fp32)
    {
        dim3 g(NN / 128, NPROJ / 256, BB);   // (18, 6, 8)
        gemm_f16<0><<<g, 256, GEMM_SMEM>>>(bq, bk, bv, nullptr);
    }

    // 2) pack kv j-pairs to half2
    kv_repack<<<BB * KAH * 256 / 256, 256>>>();

    // 3) attention GEMM + fused final epilogue -> out
    {
        dim3 g(NN / 128, NKV / 256, BB);     // (18, 4, 8)
        gemm_f16<1><<<g, 256, GEMM_SMEM>>>(bq, bk, bv, out);
    }
}

// round 8
// speedup vs baseline: 6.0911x; 1.0367x over previous
#include <cuda_runtime.h>
#include <cuda_fp16.h>
#include <math.h>
#include <stdint.h>

// Problem constants
#define BB 8
#define CC 512
#define NN 2304          // 48*48
#define NPROJ 1536       // q(512) | interleaved k,v (1024)
#define NKV 1024         // interleaved pairs: col 2c=ekv_c, 2c+1=ek_c
#define KPH 256          // half2 K-rows for projection (CC/2)
#define KAH 1152         // half2 K-rows for attention (NN/2)

// ---------------------------------------------------------------------------
// Scratch (device globals; allocation-free per harness rules)
// ---------------------------------------------------------------------------
__device__ uint32_t g_xh [BB * KPH * NN];    // half2(x[2cp][i], x[2cp+1][i])
__device__ uint32_t g_yh [BB * KPH * NN];
__device__ uint32_t g_wh [KPH * NPROJ];      // half2 W^T, n = q | k,v interleaved
__device__ uint32_t g_ebh[KAH * NN];         // half2(eb[i][2jp], eb[i][2jp+1]) [jp][i]
__device__ float    g_sq [BB * NN * CC];     // sigmoid(q) [b][i][c]
__device__ uint32_t g_kvh[BB * KAH * NKV];   // half2 over j-pairs [b][jp][c2]

// ---------------------------------------------------------------------------
// Helpers
// ---------------------------------------------------------------------------
__device__ __forceinline__ uint32_t packh2(float lo, float hi) {
    __half2 h = __floats2half2_rn(lo, hi);
    return *reinterpret_cast<uint32_t*>(&h);
}

__device__ __forceinline__ void mma_f16(float c[4], const uint32_t a[4],
                                        const uint32_t b[2]) {
    asm volatile(
        "mma.sync.aligned.m16n8k16.row.col.f32.f16.f16.f32 "
        "{%0,%1,%2,%3},{%4,%5,%6,%7},{%8,%9},{%0,%1,%2,%3};\n"
        : "+f"(c[0]), "+f"(c[1]), "+f"(c[2]), "+f"(c[3])
        : "r"(a[0]), "r"(a[1]), "r"(a[2]), "r"(a[3]), "r"(b[0]), "r"(b[1]));
}

__device__ __forceinline__ uint32_t smem_u32(const void* p) {
    uint32_t a;
    asm("{ .reg .u64 t; cvta.to.shared.u64 t, %1; cvt.u32.u64 %0, t; }"
        : "=r"(a) : "l"(p));
    return a;
}

__device__ __forceinline__ void cp16(uint32_t saddr, const void* gptr) {
    asm volatile("cp.async.cg.shared.global [%0], [%1], 16;"
                 :: "r"(saddr), "l"(gptr));
}
#define CP_COMMIT() asm volatile("cp.async.commit_group;" ::: "memory")
#define CP_WAIT(n)  asm volatile("cp.async.wait_group %0;" :: "n"(n) : "memory")

// ---------------------------------------------------------------------------
// prep_all: one kernel, 4 block ranges
// ---------------------------------------------------------------------------
#define PB_XY 4608
#define PB_W  1536
#define PB_EB 2592
#define PREP_BLOCKS (2 * PB_XY + PB_W + PB_EB)   // 13344

__global__ void __launch_bounds__(256)
prep_all(const float* __restrict__ x, const float* __restrict__ y,
         const float* __restrict__ Wq, const float* __restrict__ Wk,
         const float* __restrict__ Wv, const float* __restrict__ pb) {
    const int tid = threadIdx.x;
    const int blk = blockIdx.x;

    if (blk < 2 * PB_XY) {
        const bool isx = blk < PB_XY;
        const float* src = isx ? x : y;
        uint32_t* dst = isx ? g_xh : g_yh;
        int v = (isx ? blk : blk - PB_XY) * 256 + tid;
        int b  = v / (256 * 576);
        int r  = v % (256 * 576);
        int cp = r / 576;
        int i  = (r % 576) * 4;
        const float* base = src + ((size_t)(b * CC + 2 * cp)) * NN + i;
        float4 lo = *(const float4*)(base);
        float4 hi = *(const float4*)(base + NN);
        uint4 o;
        o.x = packh2(lo.x, hi.x); o.y = packh2(lo.y, hi.y);
        o.z = packh2(lo.z, hi.z); o.w = packh2(lo.w, hi.w);
        *(uint4*)(dst + ((size_t)(b * KPH + cp)) * NN + i) = o;
    } else if (blk < 2 * PB_XY + PB_W) {
        int v = (blk - 2 * PB_XY) * 256 + tid;
        int kp = v / NPROJ;
        int n  = v % NPROJ;
        const float* W;
        int c;
        if (n < 512) { W = Wq; c = n; }
        else {
            int m = n - 512;
            c = m >> 1;
            W = (m & 1) ? Wv : Wk;
        }
        float a = W[(size_t)c * CC + 2 * kp];
        float bv_ = W[(size_t)c * CC + 2 * kp + 1];
        g_wh[(size_t)kp * NPROJ + n] = packh2(a, bv_);
    } else {
        __shared__ float s[32][65];
        int t = blk - (2 * PB_XY + PB_W);
        int ti = t % 72, tj = t / 72;
        int i0 = ti * 32, j0 = tj * 64;
        int il = tid >> 3;
        int jq = (tid & 7) * 8;
        const float* p = pb + (size_t)(i0 + il) * NN + j0 + jq;
        float4 p0 = *(const float4*)(p);
        float4 p1 = *(const float4*)(p + 4);
        s[il][jq + 0] = __expf(p0.x); s[il][jq + 1] = __expf(p0.y);
        s[il][jq + 2] = __expf(p0.z); s[il][jq + 3] = __expf(p0.w);
        s[il][jq + 4] = __expf(p1.x); s[il][jq + 5] = __expf(p1.y);
        s[il][jq + 6] = __expf(p1.z); s[il][jq + 7] = __expf(p1.w);
        __syncthreads();
        #pragma unroll
        for (int k = 0; k < 4; k++) {
            int idx = tid + k * 256;
            int jpl = idx >> 5;
            int i_l = idx & 31;
            g_ebh[(size_t)(tj * 32 + jpl) * NN + i0 + i_l] =
                packh2(s[i_l][2 * jpl], s[i_l][2 * jpl + 1]);
        }
    }
}

// ---------------------------------------------------------------------------
// fp16 GEMM core: BM=128 BN=256, K-chunk = 32 half2-rows, 256 thr,
// warp 64x64, 4-stage cp.async ring, register-level fragment double-buffer.
// MODE 0: projection (epilogue writes g_sq and shfl-packed g_kvh directly)
// MODE 1: attention  (fused sq*num/den + transpose out)
// ---------------------------------------------------------------------------
#define SAH 136
#define SBH 264
#define ABUFH (32 * SAH)          // 4352 u32
#define BBUFH (32 * SBH)          // 8448 u32
#define STG 4
#define GEMM_SMEM (STG * (ABUFH + BBUFH) * 4)   // 204800 B

template <int MODE>
__global__ void __launch_bounds__(256)
gemm_f16(const float* __restrict__ bq, const float* __restrict__ bk,
         const float* __restrict__ bv, float* __restrict__ out) {
    extern __shared__ uint32_t smu[];
    const uint32_t smb = smem_u32(smu);

    const int b  = blockIdx.z;
    const int m0 = blockIdx.x * 128;
    const int n0 = blockIdx.y * 256;
    const int tid = threadIdx.x;

    const uint32_t* Ag;
    const uint32_t* Bg;
    int ldaH, ldbH, nch;
    if (MODE == 0) {
        Ag = ((blockIdx.y < 2) ? g_xh : g_yh) + (size_t)b * KPH * NN;
        Bg = g_wh;
        ldaH = NN; ldbH = NPROJ; nch = KPH / 32;     // 8
    } else {
        Ag = g_ebh;
        Bg = g_kvh + (size_t)b * KAH * NKV;
        ldaH = NN; ldbH = NKV; nch = KAH / 32;       // 36
    }

    const int wid = tid >> 5;
    const int mw = (wid & 1) * 64;
    const int nw = (wid >> 1) * 64;
    const int lane = tid & 31;
    const int lq = lane & 3;
    const int lr = lane >> 2;

    const int a_kr = tid >> 5, a_ic = (tid & 31) << 2;
    const int b_kr = tid >> 6, b_nc = (tid & 63) << 2;

    auto loadAsync = [&](int ck, int buf) {
        const uint32_t sA = smb + (buf * ABUFH) * 4;
        const uint32_t sB = smb + (STG * ABUFH + buf * BBUFH) * 4;
        #pragma unroll
        for (int r = 0; r < 4; r++) {
            int kr = a_kr + r * 8;
            cp16(sA + (kr * SAH + a_ic) * 4,
                 Ag + (size_t)(ck * 32 + kr) * ldaH + m0 + a_ic);
        }
        #pragma unroll
        for (int r = 0; r < 8; r++) {
            int kr = b_kr + r * 4;
            cp16(sB + (kr * SBH + b_nc) * 4,
                 Bg + (size_t)(ck * 32 + kr) * ldbH + n0 + b_nc);
        }
    };

    float acc[4][8][4];
    #pragma unroll
    for (int i = 0; i < 4; i++)
        #pragma unroll
        for (int j = 0; j < 8; j++)
            #pragma unroll
            for (int l = 0; l < 4; l++) acc[i][j][l] = 0.f;

    uint32_t af[2][4][4], bf[2][8][2];

    // Prologue: stages 0..STG-2 in flight
    #pragma unroll
    for (int s = 0; s < STG - 1; s++) {
        loadAsync(s, s);
        CP_COMMIT();
    }

    for (int c = 0; c < nch; c++) {
        CP_WAIT(STG - 2);
        __syncthreads();
        if (c + STG - 1 < nch) loadAsync(c + STG - 1, (c + STG - 1) & (STG - 1));
        CP_COMMIT();

        const uint32_t* As = smu + (c & (STG - 1)) * ABUFH;
        const uint32_t* Bs = smu + STG * ABUFH + (c & (STG - 1)) * BBUFH;

        // Fragment loads for a given ka into register buffer pb_
        auto ldfrag = [&](int ka, int pb_) {
            const int kp = 8 * ka + lq;
            #pragma unroll
            for (int mi = 0; mi < 4; mi++) {
                int base = kp * SAH + mw + 16 * mi + lr;
                af[pb_][mi][0] = As[base];
                af[pb_][mi][1] = As[base + 8];
                af[pb_][mi][2] = As[base + 4 * SAH];
                af[pb_][mi][3] = As[base + 4 * SAH + 8];
            }
            #pragma unroll
            for (int ni = 0; ni < 8; ni++) {
                int base = kp * SBH + nw + 8 * ni + lr;
                bf[pb_][ni][0] = Bs[base];
                bf[pb_][ni][1] = Bs[base + 4 * SBH];
            }
        };

        ldfrag(0, 0);
        #pragma unroll
        for (int ka = 0; ka < 4; ka++) {
            if (ka < 3) ldfrag(ka + 1, (ka + 1) & 1);   // prefetch next frags
            const int cb = ka & 1;
            #pragma unroll
            for (int mi = 0; mi < 4; mi++)
                #pragma unroll
                for (int ni = 0; ni < 8; ni++)
                    mma_f16(acc[mi][ni], af[cb][mi], bf[cb][ni]);
        }
    }

    // ------------------------------- Epilogues -----------------------------
    if (MODE == 0) {
        if (n0 < 512) {
            float* sq = g_sq + (size_t)b * NN * CC;
            #pragma unroll
            for (int mi = 0; mi < 4; mi++) {
                #pragma unroll
                for (int ni = 0; ni < 8; ni++) {
                    int row = m0 + mw + 16 * mi + lr;
                    int col = n0 + nw + 8 * ni + 2 * lq;
                    float b0 = bq[col], b1 = bq[col + 1];
                    float* a = acc[mi][ni];
                    float2 v0, v1;
                    v0.x = __fdividef(1.f, 1.f + __expf(-(a[0] + b0)));
                    v0.y = __fdividef(1.f, 1.f + __expf(-(a[1] + b1)));
                    v1.x = __fdividef(1.f, 1.f + __expf(-(a[2] + b0)));
                    v1.y = __fdividef(1.f, 1.f + __expf(-(a[3] + b1)));
                    *(float2*)(sq + (size_t)row * CC + col) = v0;
                    *(float2*)(sq + (size_t)(row + 8) * CC + col) = v1;
                }
            }
        } else {
            // kv region: even frag col = k_c, odd = v_c.
            // Pack j-pairs via shfl_xor(4) (lane^4 <=> lr^1) and write g_kvh
            // half2 directly: rows (base+2t, base+2t+1) from lanes lr=2t,2t+1.
            uint32_t* kvh = g_kvh + (size_t)b * KAH * NKV;
            const bool evenR = (lr & 1) == 0;
            #pragma unroll
            for (int mi = 0; mi < 4; mi++) {
                int rbase = m0 + mw + 16 * mi + lr;   // global j for v0 block
                #pragma unroll
                for (int ni = 0; ni < 8; ni++) {
                    int col = n0 + nw + 8 * ni + 2 * lq - 512;   // even c2
                    int ch = col >> 1;
                    float bkc = bk[ch], bvc = bv[ch];
                    float* a = acc[mi][ni];
                    float e0  = __expf(a[0] + bkc);
                    float ev0 = e0 * (a[1] + bvc);
                    float e1  = __expf(a[2] + bkc);
                    float ev1 = e1 * (a[3] + bvc);
                    // partner (lr^1) values
                    float pe0  = __shfl_xor_sync(0xffffffffu, e0, 4);
                    float pev0 = __shfl_xor_sync(0xffffffffu, ev0, 4);
                    float pe1  = __shfl_xor_sync(0xffffffffu, e1, 4);
                    float pev1 = __shfl_xor_sync(0xffffffffu, ev1, 4);
                    if (evenR) {
                        // pair (rbase, rbase+1): mine is even row -> lo
                        uint2 w0;
                        w0.x = packh2(ev0, pev0);   // ekv column
                        w0.y = packh2(e0, pe0);     // ek column
                        *(uint2*)(kvh + (size_t)(rbase >> 1) * NKV + col) = w0;
                        // pair (rbase+8, rbase+9) from v1 block
                        uint2 w1;
                        w1.x = packh2(ev1, pev1);
                        w1.y = packh2(e1, pe1);
                        *(uint2*)(kvh + (size_t)((rbase + 8) >> 1) * NKV + col) = w1;
                    }
                }
            }
        }
    } else {
        __syncthreads();
        float* so = (float*)smu;   // [c_local][m_local] stride 136
        const float* sq = g_sq + (size_t)b * NN * CC;
        const int gc0 = n0 >> 1;
        #pragma unroll
        for (int mi = 0; mi < 4; mi++) {
            #pragma unroll
            for (int ni = 0; ni < 8; ni++) {
                int rowm = mw + 16 * mi + lr;
                int cl = (nw >> 1) + 4 * ni + lq;
                int gi = m0 + rowm;
                int gc = gc0 + cl;
                float* a = acc[mi][ni];
                float s0 = sq[(size_t)gi * CC + gc];
                float s1 = sq[(size_t)(gi + 8) * CC + gc];
                so[cl * 136 + rowm]     = s0 * __fdividef(a[0], a[1]);
                so[cl * 136 + rowm + 8] = s1 * __fdividef(a[2], a[3]);
            }
        }
        __syncthreads();
        float* o = out + (size_t)b * CC * NN;
        #pragma unroll
        for (int r2 = 0; r2 < 16; r2++) {
            int v = tid + r2 * 256;
            int cl = v >> 5, m4 = (v & 31) << 2;
            float4 val = *(float4*)(so + cl * 136 + m4);
            *(float4*)(o + (size_t)(gc0 + cl) * NN + m0 + m4) = val;
        }
    }
}

// ---------------------------------------------------------------------------
// Launch.  Order: 0 prep_all, 1 proj, 2 attn
// ---------------------------------------------------------------------------
extern "C" void kernel_launch(void* const* d_in, const int* in_sizes, int n_in,
                              void* d_out, int out_size) {
    const float* x  = (const float*)d_in[0];
    const float* y  = (const float*)d_in[1];
    const float* Wq = (const float*)d_in[2];
    const float* bq = (const float*)d_in[3];
    const float* Wk = (const float*)d_in[4];
    const float* bk = (const float*)d_in[5];
    const float* Wv = (const float*)d_in[6];
    const float* bv = (const float*)d_in[7];
    const float* pb = (const float*)d_in[8];
    float* out = (float*)d_out;

    static bool attr_done = false;
    if (!attr_done) {
        cudaFuncSetAttribute(gemm_f16<0>,
                             cudaFuncAttributeMaxDynamicSharedMemorySize, GEMM_SMEM);
        cudaFuncSetAttribute(gemm_f16<1>,
                             cudaFuncAttributeMaxDynamicSharedMemorySize, GEMM_SMEM);
        attr_done = true;
    }

    // 0) all operand prep in one kernel
    prep_all<<<PREP_BLOCKS, 256>>>(x, y, Wq, Wk, Wv, pb);

    // 1) fused projection GEMM -> g_sq (fp32), g_kvh (half2, shfl-packed)
    {
        dim3 g(NN / 128, NPROJ / 256, BB);   // (18, 6, 8)
        gemm_f16<0><<<g, 256, GEMM_SMEM>>>(bq, bk, bv, nullptr);
    }

    // 2) attention GEMM + fused final epilogue -> out
    {
        dim3 g(NN / 128, NKV / 256, BB);     // (18, 4, 8)
        gemm_f16<1><<<g, 256, GEMM_SMEM>>>(bq, bk, bv, out);
    }
}

// round 9
// speedup vs baseline: 6.1541x; 1.0103x over previous
#include <cuda_runtime.h>
#include <cuda_fp16.h>
#include <math.h>
#include <stdint.h>

// Problem constants
#define BB 8
#define CC 512
#define NN 2304          // 48*48
#define NPROJ 1536       // q(512) | interleaved k,v (1024)
#define NKV 1024         // interleaved pairs: col 2c=ekv_c, 2c+1=ek_c
#define KPH 256          // half2 K-rows for projection (CC/2)
#define KAH 1152         // half2 K-rows for attention (NN/2)

// ---------------------------------------------------------------------------
// Scratch (device globals; allocation-free per harness rules)
// ---------------------------------------------------------------------------
__device__ uint32_t g_xh [BB * KPH * NN];    // half2(x[2cp][i], x[2cp+1][i])
__device__ uint32_t g_yh [BB * KPH * NN];
__device__ uint32_t g_wh [KPH * NPROJ];      // half2 W^T, n = q | k,v interleaved
__device__ uint32_t g_ebh[KAH * NN];         // half2(eb[i][2jp], eb[i][2jp+1]) [jp][i]
__device__ float    g_sq [BB * NN * CC];     // sigmoid(q) [b][i][c]
__device__ uint32_t g_kvh[BB * KAH * NKV];   // half2 over j-pairs [b][jp][c2]

// ---------------------------------------------------------------------------
// Helpers
// ---------------------------------------------------------------------------
__device__ __forceinline__ uint32_t packh2(float lo, float hi) {
    __half2 h = __floats2half2_rn(lo, hi);
    return *reinterpret_cast<uint32_t*>(&h);
}

__device__ __forceinline__ void mma_f16(float c[4], const uint32_t a[4],
                                        const uint32_t b[2]) {
    asm volatile(
        "mma.sync.aligned.m16n8k16.row.col.f32.f16.f16.f32 "
        "{%0,%1,%2,%3},{%4,%5,%6,%7},{%8,%9},{%0,%1,%2,%3};\n"
        : "+f"(c[0]), "+f"(c[1]), "+f"(c[2]), "+f"(c[3])
        : "r"(a[0]), "r"(a[1]), "r"(a[2]), "r"(a[3]), "r"(b[0]), "r"(b[1]));
}

__device__ __forceinline__ uint32_t smem_u32(const void* p) {
    uint32_t a;
    asm("{ .reg .u64 t; cvta.to.shared.u64 t, %1; cvt.u32.u64 %0, t; }"
        : "=r"(a) : "l"(p));
    return a;
}

__device__ __forceinline__ void cp16(uint32_t saddr, const void* gptr) {
    asm volatile("cp.async.cg.shared.global [%0], [%1], 16;"
                 :: "r"(saddr), "l"(gptr));
}
#define CP_COMMIT() asm volatile("cp.async.commit_group;" ::: "memory")
#define CP_WAIT(n)  asm volatile("cp.async.wait_group %0;" :: "n"(n) : "memory")

// ---------------------------------------------------------------------------
// prep_all: one kernel, 4 block ranges (unchanged from R8)
// ---------------------------------------------------------------------------
#define PB_XY 4608
#define PB_W  1536
#define PB_EB 2592
#define PREP_BLOCKS (2 * PB_XY + PB_W + PB_EB)   // 13344

__global__ void __launch_bounds__(256)
prep_all(const float* __restrict__ x, const float* __restrict__ y,
         const float* __restrict__ Wq, const float* __restrict__ Wk,
         const float* __restrict__ Wv, const float* __restrict__ pb) {
    const int tid = threadIdx.x;
    const int blk = blockIdx.x;

    if (blk < 2 * PB_XY) {
        const bool isx = blk < PB_XY;
        const float* src = isx ? x : y;
        uint32_t* dst = isx ? g_xh : g_yh;
        int v = (isx ? blk : blk - PB_XY) * 256 + tid;
        int b  = v / (256 * 576);
        int r  = v % (256 * 576);
        int cp = r / 576;
        int i  = (r % 576) * 4;
        const float* base = src + ((size_t)(b * CC + 2 * cp)) * NN + i;
        float4 lo = *(const float4*)(base);
        float4 hi = *(const float4*)(base + NN);
        uint4 o;
        o.x = packh2(lo.x, hi.x); o.y = packh2(lo.y, hi.y);
        o.z = packh2(lo.z, hi.z); o.w = packh2(lo.w, hi.w);
        *(uint4*)(dst + ((size_t)(b * KPH + cp)) * NN + i) = o;
    } else if (blk < 2 * PB_XY + PB_W) {
        int v = (blk - 2 * PB_XY) * 256 + tid;
        int kp = v / NPROJ;
        int n  = v % NPROJ;
        const float* W;
        int c;
        if (n < 512) { W = Wq; c = n; }
        else {
            int m = n - 512;
            c = m >> 1;
            W = (m & 1) ? Wv : Wk;
        }
        float a = W[(size_t)c * CC + 2 * kp];
        float bv_ = W[(size_t)c * CC + 2 * kp + 1];
        g_wh[(size_t)kp * NPROJ + n] = packh2(a, bv_);
    } else {
        __shared__ float s[32][65];
        int t = blk - (2 * PB_XY + PB_W);
        int ti = t % 72, tj = t / 72;
        int i0 = ti * 32, j0 = tj * 64;
        int il = tid >> 3;
        int jq = (tid & 7) * 8;
        const float* p = pb + (size_t)(i0 + il) * NN + j0 + jq;
        float4 p0 = *(const float4*)(p);
        float4 p1 = *(const float4*)(p + 4);
        s[il][jq + 0] = __expf(p0.x); s[il][jq + 1] = __expf(p0.y);
        s[il][jq + 2] = __expf(p0.z); s[il][jq + 3] = __expf(p0.w);
        s[il][jq + 4] = __expf(p1.x); s[il][jq + 5] = __expf(p1.y);
        s[il][jq + 6] = __expf(p1.z); s[il][jq + 7] = __expf(p1.w);
        __syncthreads();
        #pragma unroll
        for (int k = 0; k < 4; k++) {
            int idx = tid + k * 256;
            int jpl = idx >> 5;
            int i_l = idx & 31;
            g_ebh[(size_t)(tj * 32 + jpl) * NN + i0 + i_l] =
                packh2(s[i_l][2 * jpl], s[i_l][2 * jpl + 1]);
        }
    }
}

// ---------------------------------------------------------------------------
// fp16 GEMM core: BM=128 BN=128, K-chunk = 32 half2-rows, 256 thr,
// 8 warps as 4(m) x 2(n), warp tile 32x64, 3-stage cp.async ring.
// Sized for 2 CTAs/SM (smem 104KB, regs <=128 via launch_bounds).
// MODE 0: projection (epilogue writes g_sq and shfl-packed g_kvh directly)
// MODE 1: attention  (fused sq*num/den + transpose out)
// ---------------------------------------------------------------------------
#define SAH 136
#define ABUFH (32 * SAH)          // 4352 u32 (A and B tiles same size)
#define STG 3
#define GEMM_SMEM (STG * 2 * ABUFH * 4)   // 104448 B

template <int MODE>
__global__ void __launch_bounds__(256, 2)
gemm_f16(const float* __restrict__ bq, const float* __restrict__ bk,
         const float* __restrict__ bv, float* __restrict__ out) {
    extern __shared__ uint32_t smu[];
    const uint32_t smb = smem_u32(smu);

    const int b  = blockIdx.z;
    const int m0 = blockIdx.x * 128;
    const int n0 = blockIdx.y * 128;
    const int tid = threadIdx.x;

    const uint32_t* Ag;
    const uint32_t* Bg;
    int ldaH, ldbH, nch;
    if (MODE == 0) {
        Ag = ((blockIdx.y < 4) ? g_xh : g_yh) + (size_t)b * KPH * NN;
        Bg = g_wh;
        ldaH = NN; ldbH = NPROJ; nch = KPH / 32;     // 8
    } else {
        Ag = g_ebh;
        Bg = g_kvh + (size_t)b * KAH * NKV;
        ldaH = NN; ldbH = NKV; nch = KAH / 32;       // 36
    }

    const int wid = tid >> 5;
    const int mw = (wid & 3) * 32;        // 4 m-warps
    const int nw = (wid >> 2) * 64;       // 2 n-warps
    const int lane = tid & 31;
    const int lq = lane & 3;
    const int lr = lane >> 2;

    // Per-thread cp.async indices (A and B tiles both 32 rows x 128 u32)
    const int t_kr = tid >> 5, t_ic = (tid & 31) << 2;

    auto loadAsync = [&](int ck, int buf) {
        const uint32_t sA = smb + (buf * ABUFH) * 4;
        const uint32_t sB = smb + ((STG + buf) * ABUFH) * 4;
        #pragma unroll
        for (int r = 0; r < 4; r++) {
            int kr = t_kr + r * 8;
            cp16(sA + (kr * SAH + t_ic) * 4,
                 Ag + (size_t)(ck * 32 + kr) * ldaH + m0 + t_ic);
        }
        #pragma unroll
        for (int r = 0; r < 4; r++) {
            int kr = t_kr + r * 8;
            cp16(sB + (kr * SAH + t_ic) * 4,
                 Bg + (size_t)(ck * 32 + kr) * ldbH + n0 + t_ic);
        }
    };

    float acc[2][8][4];
    #pragma unroll
    for (int i = 0; i < 2; i++)
        #pragma unroll
        for (int j = 0; j < 8; j++)
            #pragma unroll
            for (int l = 0; l < 4; l++) acc[i][j][l] = 0.f;

    // Prologue: stages 0..STG-2 in flight
    #pragma unroll
    for (int s = 0; s < STG - 1; s++) {
        loadAsync(s, s);
        CP_COMMIT();
    }

    int buf = 0;
    for (int c = 0; c < nch; c++) {
        CP_WAIT(STG - 2);
        __syncthreads();
        if (c + STG - 1 < nch) {
            int nb = c + STG - 1;
            loadAsync(nb, nb % STG);
        }
        CP_COMMIT();

        const uint32_t* As = smu + buf * ABUFH;
        const uint32_t* Bs = smu + (STG + buf) * ABUFH;
        #pragma unroll
        for (int ka = 0; ka < 4; ka++) {
            uint32_t af[2][4], bf[8][2];
            const int kp = 8 * ka + lq;
            #pragma unroll
            for (int mi = 0; mi < 2; mi++) {
                int base = kp * SAH + mw + 16 * mi + lr;
                af[mi][0] = As[base];
                af[mi][1] = As[base + 8];
                af[mi][2] = As[base + 4 * SAH];
                af[mi][3] = As[base + 4 * SAH + 8];
            }
            #pragma unroll
            for (int ni = 0; ni < 8; ni++) {
                int base = kp * SAH + nw + 8 * ni + lr;
                bf[ni][0] = Bs[base];
                bf[ni][1] = Bs[base + 4 * SAH];
            }
            #pragma unroll
            for (int mi = 0; mi < 2; mi++)
                #pragma unroll
                for (int ni = 0; ni < 8; ni++)
                    mma_f16(acc[mi][ni], af[mi], bf[ni]);
        }
        buf++;
        if (buf == STG) buf = 0;
    }

    // ------------------------------- Epilogues -----------------------------
    if (MODE == 0) {
        if (n0 < 512) {
            float* sq = g_sq + (size_t)b * NN * CC;
            #pragma unroll
            for (int mi = 0; mi < 2; mi++) {
                #pragma unroll
                for (int ni = 0; ni < 8; ni++) {
                    int row = m0 + mw + 16 * mi + lr;
                    int col = n0 + nw + 8 * ni + 2 * lq;
                    float b0 = bq[col], b1 = bq[col + 1];
                    float* a = acc[mi][ni];
                    float2 v0, v1;
                    v0.x = __fdividef(1.f, 1.f + __expf(-(a[0] + b0)));
                    v0.y = __fdividef(1.f, 1.f + __expf(-(a[1] + b1)));
                    v1.x = __fdividef(1.f, 1.f + __expf(-(a[2] + b0)));
                    v1.y = __fdividef(1.f, 1.f + __expf(-(a[3] + b1)));
                    *(float2*)(sq + (size_t)row * CC + col) = v0;
                    *(float2*)(sq + (size_t)(row + 8) * CC + col) = v1;
                }
            }
        } else {
            // kv region: even frag col = k_c, odd = v_c.
            // Pack j-pairs via shfl_xor(4) (partner lr^1) and write g_kvh.
            uint32_t* kvh = g_kvh + (size_t)b * KAH * NKV;
            const bool evenR = (lr & 1) == 0;
            #pragma unroll
            for (int mi = 0; mi < 2; mi++) {
                int rbase = m0 + mw + 16 * mi + lr;
                #pragma unroll
                for (int ni = 0; ni < 8; ni++) {
                    int col = n0 + nw + 8 * ni + 2 * lq - 512;   // even c2
                    int ch = col >> 1;
                    float bkc = bk[ch], bvc = bv[ch];
                    float* a = acc[mi][ni];
                    float e0  = __expf(a[0] + bkc);
                    float ev0 = e0 * (a[1] + bvc);
                    float e1  = __expf(a[2] + bkc);
                    float ev1 = e1 * (a[3] + bvc);
                    float pe0  = __shfl_xor_sync(0xffffffffu, e0, 4);
                    float pev0 = __shfl_xor_sync(0xffffffffu, ev0, 4);
                    float pe1  = __shfl_xor_sync(0xffffffffu, e1, 4);
                    float pev1 = __shfl_xor_sync(0xffffffffu, ev1, 4);
                    if (evenR) {
                        uint2 w0;
                        w0.x = packh2(ev0, pev0);
                        w0.y = packh2(e0, pe0);
                        *(uint2*)(kvh + (size_t)(rbase >> 1) * NKV + col) = w0;
                        uint2 w1;
                        w1.x = packh2(ev1, pev1);
                        w1.y = packh2(e1, pe1);
                        *(uint2*)(kvh + (size_t)((rbase + 8) >> 1) * NKV + col) = w1;
                    }
                }
            }
        }
    } else {
        // attn: even col = num, odd = den -> sq * num/den -> transpose -> out
        __syncthreads();
        float* so = (float*)smu;   // [c_local 0..63][m_local 0..127] stride 136
        const float* sq = g_sq + (size_t)b * NN * CC;
        const int gc0 = n0 >> 1;   // 64 channels per CTA
        #pragma unroll
        for (int mi = 0; mi < 2; mi++) {
            #pragma unroll
            for (int ni = 0; ni < 8; ni++) {
                int rowm = mw + 16 * mi + lr;
                int cl = (nw >> 1) + 4 * ni + lq;    // 0..63
                int gi = m0 + rowm;
                int gc = gc0 + cl;
                float* a = acc[mi][ni];
                float s0 = sq[(size_t)gi * CC + gc];
                float s1 = sq[(size_t)(gi + 8) * CC + gc];
                so[cl * 136 + rowm]     = s0 * __fdividef(a[0], a[1]);
                so[cl * 136 + rowm + 8] = s1 * __fdividef(a[2], a[3]);
            }
        }
        __syncthreads();
        float* o = out + (size_t)b * CC * NN;
        #pragma unroll
        for (int r2 = 0; r2 < 8; r2++) {
            int v = tid + r2 * 256;
            int cl = v >> 5, m4 = (v & 31) << 2;
            float4 val = *(float4*)(so + cl * 136 + m4);
            *(float4*)(o + (size_t)(gc0 + cl) * NN + m0 + m4) = val;
        }
    }
}

// ---------------------------------------------------------------------------
// Launch.  Order: 0 prep_all, 1 proj, 2 attn
// ---------------------------------------------------------------------------
extern "C" void kernel_launch(void* const* d_in, const int* in_sizes, int n_in,
                              void* d_out, int out_size) {
    const float* x  = (const float*)d_in[0];
    const float* y  = (const float*)d_in[1];
    const float* Wq = (const float*)d_in[2];
    const float* bq = (const float*)d_in[3];
    const float* Wk = (const float*)d_in[4];
    const float* bk = (const float*)d_in[5];
    const float* Wv = (const float*)d_in[6];
    const float* bv = (const float*)d_in[7];
    const float* pb = (const float*)d_in[8];
    float* out = (float*)d_out;

    static bool attr_done = false;
    if (!attr_done) {
        cudaFuncSetAttribute(gemm_f16<0>,
                             cudaFuncAttributeMaxDynamicSharedMemorySize, GEMM_SMEM);
        cudaFuncSetAttribute(gemm_f16<1>,
                             cudaFuncAttributeMaxDynamicSharedMemorySize, GEMM_SMEM);
        attr_done = true;
    }

    // 0) all operand prep in one kernel
    prep_all<<<PREP_BLOCKS, 256>>>(x, y, Wq, Wk, Wv, pb);

    // 1) fused projection GEMM -> g_sq (fp32), g_kvh (half2, shfl-packed)
    {
        dim3 g(NN / 128, NPROJ / 128, BB);   // (18, 12, 8)
        gemm_f16<0><<<g, 256, GEMM_SMEM>>>(bq, bk, bv, nullptr);
    }

    // 2) attention GEMM + fused final epilogue -> out
    {
        dim3 g(NN / 128, NKV / 128, BB);     // (18, 8, 8)
        gemm_f16<1><<<g, 256, GEMM_SMEM>>>(bq, bk, bv, out);
    }
}

// round 10
// speedup vs baseline: 6.7925x; 1.1037x over previous
#include <cuda_runtime.h>
#include <cuda_fp16.h>
#include <math.h>
#include <stdint.h>

// Problem constants
#define BB 8
#define CC 512
#define NN 2304          // 48*48
#define NPROJ 1536       // q(512) | interleaved k,v (1024)
#define NKV 1024         // interleaved pairs: col 2c=ekv_c, 2c+1=ek_c
#define MGT 144          // NN/16 m-groups (M = NN for both GEMMs)
#define KOCT_P 32        // CC/16 k-octs (projection K)
#define KOCT_A 144       // NN/16 k-octs (attention K)

// ---------------------------------------------------------------------------
// Scratch — MMA-native layouts.
// A-native: uint4 at [koct][mg][lane(lr*4+lq)] = full m16k16 A-frag:
//   {h2(m,kp=lq), h2(m+8,lq), h2(m,lq+4), h2(m+8,lq+4)}, m=mg*16+lr, kp rel koct*8
// B-native: uint2 at [koct][n][lq] = full k16n8 B-frag: {h2(n,kp=lq), h2(n,lq+4)}
// ---------------------------------------------------------------------------
__device__ uint4 g_x4 [(size_t)BB * KOCT_P * MGT * 32];
__device__ uint4 g_y4 [(size_t)BB * KOCT_P * MGT * 32];
__device__ uint4 g_eb4[(size_t)KOCT_A * MGT * 32];
__device__ uint2 g_w2 [(size_t)KOCT_P * NPROJ * 4];
__device__ uint2 g_kv2[(size_t)BB * KOCT_A * NKV * 4];
__device__ float g_sq [(size_t)BB * NN * CC];      // sigmoid(q) [b][i][c]

// ---------------------------------------------------------------------------
// Helpers
// ---------------------------------------------------------------------------
__device__ __forceinline__ uint32_t packh2(float lo, float hi) {
    __half2 h = __floats2half2_rn(lo, hi);
    return *reinterpret_cast<uint32_t*>(&h);
}

__device__ __forceinline__ void mma_f16(float c[4], const uint32_t* a,
                                        const uint32_t* b) {
    asm volatile(
        "mma.sync.aligned.m16n8k16.row.col.f32.f16.f16.f32 "
        "{%0,%1,%2,%3},{%4,%5,%6,%7},{%8,%9},{%0,%1,%2,%3};\n"
        : "+f"(c[0]), "+f"(c[1]), "+f"(c[2]), "+f"(c[3])
        : "r"(a[0]), "r"(a[1]), "r"(a[2]), "r"(a[3]), "r"(b[0]), "r"(b[1]));
}

__device__ __forceinline__ uint32_t smem_u32(const void* p) {
    uint32_t a;
    asm("{ .reg .u64 t; cvta.to.shared.u64 t, %1; cvt.u32.u64 %0, t; }"
        : "=r"(a) : "l"(p));
    return a;
}

__device__ __forceinline__ void cp16(uint32_t saddr, const void* gptr) {
    asm volatile("cp.async.cg.shared.global [%0], [%1], 16;"
                 :: "r"(saddr), "l"(gptr));
}
#define CP_COMMIT() asm volatile("cp.async.commit_group;" ::: "memory")
#define CP_WAIT(n)  asm volatile("cp.async.wait_group %0;" :: "n"(n) : "memory")

// ---------------------------------------------------------------------------
// prep_a_k: x/y [b][c][i] -> A-native (k = c).  grid (18, 32, 8)
// ---------------------------------------------------------------------------
__global__ void __launch_bounds__(256)
prep_a_k(const float* __restrict__ src, uint4* __restrict__ dst) {
    __shared__ float s[16][132];      // [k_local][m_local]
    const int iblk = blockIdx.x, koct = blockIdx.y, b = blockIdx.z;
    const int i0 = iblk * 128, c0 = koct * 16;
    const int tid = threadIdx.x;
    #pragma unroll
    for (int r = 0; r < 2; r++) {
        int idx = tid + r * 256;                 // 512 float4 = 16 rows x 32
        int row = idx >> 5, col4 = (idx & 31) << 2;
        float4 f = *(const float4*)(src + ((size_t)(b * CC + c0 + row)) * NN + i0 + col4);
        *(float4*)(&s[row][col4]) = f;
    }
    __syncthreads();
    const int mg = tid >> 5, lane = tid & 31, lr = lane >> 2, lq = lane & 3;
    const int m = mg * 16 + lr;
    uint4 o;
    o.x = packh2(s[2 * lq][m],     s[2 * lq + 1][m]);
    o.y = packh2(s[2 * lq][m + 8], s[2 * lq + 1][m + 8]);
    o.z = packh2(s[2 * lq + 8][m],     s[2 * lq + 9][m]);
    o.w = packh2(s[2 * lq + 8][m + 8], s[2 * lq + 9][m + 8]);
    dst[(((size_t)b * KOCT_P + koct) * MGT + iblk * 8 + mg) * 32 + lane] = o;
}

// ---------------------------------------------------------------------------
// prep_eb: pb [i][j] -> exp -> A-native (m = i, k = j).  grid (18, 144)
// ---------------------------------------------------------------------------
__global__ void __launch_bounds__(256)
prep_eb(const float* __restrict__ pb) {
    __shared__ float s[16][132];      // [j_local][i_local]
    const int iblk = blockIdx.x, koct = blockIdx.y;
    const int i0 = iblk * 128, j0 = koct * 16;
    const int tid = threadIdx.x;
    #pragma unroll
    for (int r = 0; r < 2; r++) {
        int idx = tid + r * 256;                 // 512 float4 = 128 rows x 4
        int irow = idx >> 2, j4 = (idx & 3) << 2;
        float4 f = *(const float4*)(pb + (size_t)(i0 + irow) * NN + j0 + j4);
        s[j4 + 0][irow] = __expf(f.x);
        s[j4 + 1][irow] = __expf(f.y);
        s[j4 + 2][irow] = __expf(f.z);
        s[j4 + 3][irow] = __expf(f.w);
    }
    __syncthreads();
    const int mg = tid >> 5, lane = tid & 31, lr = lane >> 2, lq = lane & 3;
    const int m = mg * 16 + lr;
    uint4 o;
    o.x = packh2(s[2 * lq][m],     s[2 * lq + 1][m]);
    o.y = packh2(s[2 * lq][m + 8], s[2 * lq + 1][m + 8]);
    o.z = packh2(s[2 * lq + 8][m],     s[2 * lq + 9][m]);
    o.w = packh2(s[2 * lq + 8][m + 8], s[2 * lq + 9][m + 8]);
    g_eb4[((size_t)koct * MGT + iblk * 8 + mg) * 32 + lane] = o;
}

// ---------------------------------------------------------------------------
// prep_w: Wq/Wk/Wv [c][k] -> B-native [koct][n][lq], n = q | k,v interleaved
// ---------------------------------------------------------------------------
__global__ void __launch_bounds__(256)
prep_w(const float* __restrict__ Wq, const float* __restrict__ Wk,
       const float* __restrict__ Wv) {
    int idx = blockIdx.x * 256 + threadIdx.x;    // KOCT_P*NPROJ*4 = 196608
    int lq = idx & 3;
    int n  = (idx >> 2) % NPROJ;
    int koct = idx / (NPROJ * 4);
    const float* W;
    int c;
    if (n < 512) { W = Wq; c = n; }
    else {
        int m = n - 512;
        c = m >> 1;
        W = (m & 1) ? Wv : Wk;
    }
    int k0 = koct * 16 + 2 * lq;
    float2 lo = *(const float2*)(W + (size_t)c * CC + k0);
    float2 hi = *(const float2*)(W + (size_t)c * CC + k0 + 8);
    uint2 o;
    o.x = packh2(lo.x, lo.y);
    o.y = packh2(hi.x, hi.y);
    g_w2[idx] = o;                               // idx == (koct*NPROJ + n)*4 + lq
}

// ---------------------------------------------------------------------------
// fp16 GEMM core: BM=128 BN=128, chunk = 4 k-octs (64 k), 256 thr,
// warps 4(m) x 2(n), warp tile 32x64, 3-stage cp.async ring, 2 CTAs/SM.
// Fragments: af = 1x LDS.128, bf = 1x LDS.64 (MMA-native smem, no padding).
// ---------------------------------------------------------------------------
#define STG 3
#define A_ST 16384
#define B_ST 16384
#define GEMM_SMEM (STG * (A_ST + B_ST))   // 98304 B

template <int MODE>
__global__ void __launch_bounds__(256, 2)
gemm_f16(const float* __restrict__ bq, const float* __restrict__ bk,
         const float* __restrict__ bv, float* __restrict__ out) {
    extern __shared__ char smem[];
    const uint32_t smb = smem_u32(smem);

    const int b  = blockIdx.z;
    const int m0 = blockIdx.x * 128;
    const int n0 = blockIdx.y * 128;
    const int tid = threadIdx.x;

    const uint4* Ag;
    const uint2* Bg;
    int Ntot, nch;
    if (MODE == 0) {
        Ag = ((blockIdx.y < 4) ? g_x4 : g_y4) + (size_t)b * KOCT_P * MGT * 32;
        Bg = g_w2;
        Ntot = NPROJ; nch = KOCT_P / 4;          // 8
    } else {
        Ag = g_eb4;
        Bg = g_kv2 + (size_t)b * KOCT_A * NKV * 4;
        Ntot = NKV; nch = KOCT_A / 4;            // 36
    }
    const int mg0 = m0 >> 4;

    const int wid = tid >> 5;
    const int mwg = (wid & 3) * 2;        // m-group base within tile (mw = mwg*16)
    const int nw  = (wid >> 2) * 64;
    const int lane = tid & 31;
    const int lq = lane & 3;
    const int lr = lane >> 2;

    auto loadAsync = [&](int ch, int st) {
        const uint32_t sA = smb + st * A_ST;
        const uint32_t sB = smb + STG * A_ST + st * B_ST;
        #pragma unroll
        for (int r = 0; r < 4; r++) {
            int ko = ch * 4 + r;
            cp16(sA + r * 4096 + tid * 16,
                 Ag + ((size_t)ko * MGT + mg0) * 32 + tid);
            cp16(sB + r * 4096 + tid * 16,
                 Bg + ((size_t)ko * Ntot + n0) * 4 + tid * 2);
        }
    };

    float acc[2][8][4];
    #pragma unroll
    for (int i = 0; i < 2; i++)
        #pragma unroll
        for (int j = 0; j < 8; j++)
            #pragma unroll
            for (int l = 0; l < 4; l++) acc[i][j][l] = 0.f;

    #pragma unroll
    for (int s = 0; s < STG - 1; s++) {
        loadAsync(s, s);
        CP_COMMIT();
    }

    int st = 0;
    for (int c = 0; c < nch; c++) {
        CP_WAIT(STG - 2);
        __syncthreads();
        if (c + STG - 1 < nch) loadAsync(c + STG - 1, (c + STG - 1) % STG);
        CP_COMMIT();

        const uint4* As4 = (const uint4*)(smem + st * A_ST);
        const uint2* Bs2 = (const uint2*)(smem + STG * A_ST + st * B_ST);
        #pragma unroll
        for (int ka = 0; ka < 4; ka++) {
            uint4 af0 = As4[ka * 256 + mwg * 32 + lane];
            uint4 af1 = As4[ka * 256 + (mwg + 1) * 32 + lane];
            uint2 bf[8];
            #pragma unroll
            for (int ni = 0; ni < 8; ni++)
                bf[ni] = Bs2[ka * 512 + nw * 4 + ni * 32 + lane];
            #pragma unroll
            for (int ni = 0; ni < 8; ni++) {
                mma_f16(acc[0][ni], (const uint32_t*)&af0, (const uint32_t*)&bf[ni]);
                mma_f16(acc[1][ni], (const uint32_t*)&af1, (const uint32_t*)&bf[ni]);
            }
        }
        st++;
        if (st == STG) st = 0;
    }

    // ------------------------------- Epilogues -----------------------------
    if (MODE == 0) {
        const int mw = (wid & 3) * 32;
        if (n0 < 512) {
            float* sq = g_sq + (size_t)b * NN * CC;
            #pragma unroll
            for (int mi = 0; mi < 2; mi++) {
                #pragma unroll
                for (int ni = 0; ni < 8; ni++) {
                    int row = m0 + mw + 16 * mi + lr;
                    int col = n0 + nw + 8 * ni + 2 * lq;
                    float b0 = bq[col], b1 = bq[col + 1];
                    float* a = acc[mi][ni];
                    float2 v0, v1;
                    v0.x = __fdividef(1.f, 1.f + __expf(-(a[0] + b0)));
                    v0.y = __fdividef(1.f, 1.f + __expf(-(a[1] + b1)));
                    v1.x = __fdividef(1.f, 1.f + __expf(-(a[2] + b0)));
                    v1.y = __fdividef(1.f, 1.f + __expf(-(a[3] + b1)));
                    *(float2*)(sq + (size_t)row * CC + col) = v0;
                    *(float2*)(sq + (size_t)(row + 8) * CC + col) = v1;
                }
            }
        } else {
            // kv region: even frag col = k_c, odd = v_c.  Emit attn B-native:
            // uint2 at [koct_j][c2][lq_j] = {h2(j0,j0+1), h2(j0+8,j0+9)},
            // j0 = 16*koct + 2*lq_j.  Frag m-span (16 rows) == one koct.
            uint2* kvh = g_kv2 + (size_t)b * KOCT_A * NKV * 4;
            const bool evenR = (lr & 1) == 0;
            const int t = lr >> 1;
            #pragma unroll
            for (int mi = 0; mi < 2; mi++) {
                int mb = m0 + mw + 16 * mi;
                int koct = mb >> 4;
                #pragma unroll
                for (int ni = 0; ni < 8; ni++) {
                    int col = n0 + nw + 8 * ni + 2 * lq - 512;   // even c2 (ekv)
                    int ch = col >> 1;
                    float bkc = bk[ch], bvc = bv[ch];
                    float* a = acc[mi][ni];
                    float e0  = __expf(a[0] + bkc);              // j = mb+lr
                    float ev0 = e0 * (a[1] + bvc);
                    float e1  = __expf(a[2] + bkc);              // j = mb+lr+8
                    float ev1 = e1 * (a[3] + bvc);
                    float pe0  = __shfl_xor_sync(0xffffffffu, e0, 4);
                    float pev0 = __shfl_xor_sync(0xffffffffu, ev0, 4);
                    float pe1  = __shfl_xor_sync(0xffffffffu, e1, 4);
                    float pev1 = __shfl_xor_sync(0xffffffffu, ev1, 4);
                    if (evenR) {
                        uint2 w0, w1;
                        w0.x = packh2(ev0, pev0);   // ekv: (j0, j0+1)
                        w0.y = packh2(ev1, pev1);   //      (j0+8, j0+9)
                        w1.x = packh2(e0, pe0);     // ek
                        w1.y = packh2(e1, pe1);
                        kvh[((size_t)koct * NKV + col) * 4 + t]     = w0;
                        kvh[((size_t)koct * NKV + col + 1) * 4 + t] = w1;
                    }
                }
            }
        }
    } else {
        // attn: even col = num, odd = den -> sq * num/den -> transpose -> out
        const int mw = (wid & 3) * 32;
        __syncthreads();
        float* so = (float*)smem;     // [c_local 0..63][m_local 0..127] stride 136
        const float* sq = g_sq + (size_t)b * NN * CC;
        const int gc0 = n0 >> 1;
        #pragma unroll
        for (int mi = 0; mi < 2; mi++) {
            #pragma unroll
            for (int ni = 0; ni < 8; ni++) {
                int rowm = mw + 16 * mi + lr;
                int cl = (nw >> 1) + 4 * ni + lq;
                int gi = m0 + rowm;
                int gc = gc0 + cl;
                float* a = acc[mi][ni];
                float s0 = sq[(size_t)gi * CC + gc];
                float s1 = sq[(size_t)(gi + 8) * CC + gc];
                so[cl * 136 + rowm]     = s0 * __fdividef(a[0], a[1]);
                so[cl * 136 + rowm + 8] = s1 * __fdividef(a[2], a[3]);
            }
        }
        __syncthreads();
        float* o = out + (size_t)b * CC * NN;
        #pragma unroll
        for (int r2 = 0; r2 < 8; r2++) {
            int v = tid + r2 * 256;
            int cl = v >> 5, m4 = (v & 31) << 2;
            float4 val = *(float4*)(so + cl * 136 + m4);
            *(float4*)(o + (size_t)(gc0 + cl) * NN + m0 + m4) = val;
        }
    }
}

// ---------------------------------------------------------------------------
// Launch.  Order: 0 prep_x, 1 prep_y, 2 prep_w, 3 prep_eb, 4 proj, 5 attn
// (ncu -s 5 -c 1 lands on the attention GEMM)
// ---------------------------------------------------------------------------
extern "C" void kernel_launch(void* const* d_in, const int* in_sizes, int n_in,
                              void* d_out, int out_size) {
    const float* x  = (const float*)d_in[0];
    const float* y  = (const float*)d_in[1];
    const float* Wq = (const float*)d_in[2];
    const float* bq = (const float*)d_in[3];
    const float* Wk = (const float*)d_in[4];
    const float* bk = (const float*)d_in[5];
    const float* Wv = (const float*)d_in[6];
    const float* bv = (const float*)d_in[7];
    const float* pb = (const float*)d_in[8];
    float* out = (float*)d_out;

    static bool attr_done = false;
    if (!attr_done) {
        cudaFuncSetAttribute(gemm_f16<0>,
                             cudaFuncAttributeMaxDynamicSharedMemorySize, GEMM_SMEM);
        cudaFuncSetAttribute(gemm_f16<1>,
                             cudaFuncAttributeMaxDynamicSharedMemorySize, GEMM_SMEM);
        attr_done = true;
    }

    uint4 *p_x4, *p_y4;
    cudaGetSymbolAddress((void**)&p_x4, g_x4);
    cudaGetSymbolAddress((void**)&p_y4, g_y4);

    // 0,1) x/y -> A-native
    {
        dim3 g(18, KOCT_P, BB);
        prep_a_k<<<g, 256>>>(x, p_x4);
        prep_a_k<<<g, 256>>>(y, p_y4);
    }
    // 2) W -> B-native
    prep_w<<<KOCT_P * NPROJ * 4 / 256, 256>>>(Wq, Wk, Wv);
    // 3) exp(pos_bias) -> A-native
    {
        dim3 g(18, KOCT_A);
        prep_eb<<<g, 256>>>(pb);
    }
    // 4) fused projection GEMM -> g_sq, g_kv2 (attn B-native)
    {
        dim3 g(NN / 128, NPROJ / 128, BB);   // (18, 12, 8)
        gemm_f16<0><<<g, 256, GEMM_SMEM>>>(bq, bk, bv, nullptr);
    }
    // 5) attention GEMM + fused final epilogue -> out
    {
        dim3 g(NN / 128, NKV / 128, BB);     // (18, 8, 8)
        gemm_f16<1><<<g, 256, GEMM_SMEM>>>(bq, bk, bv, out);
    }
}